// round 5
// baseline (speedup 1.0000x reference)
#include <cuda_runtime.h>
#include <math.h>

#define Bb   4
#define Hh   8
#define Tt   8192
#define Dd   64
#define Cc   64
#define Ww   128
#define BH   (Bb*Hh)
#define NROW (BH*Cc)
#define NOUT (BH*Tt*Dd)
#define QP 68
#define DP 132

typedef unsigned long long u64;

__device__ float  g_dists[(size_t)NROW * Tt];
__device__ int    g_idx[NROW * Ww];
__device__ float  g_cnt[BH * Tt];
__device__ double g_loss;

// packed fp32 pair FMA: d.lo += a.lo*b.lo ; d.hi += a.hi*b.hi
__device__ __forceinline__ void ffma2(u64 &d, u64 a, u64 b) {
    asm("fma.rn.f32x2 %0, %1, %2, %0;" : "+l"(d) : "l"(a), "l"(b));
}
__device__ __forceinline__ u64 packf2(float lo, float hi) {
    u64 r;
    asm("mov.b64 %0, {%1, %2};" : "=l"(r) : "f"(lo), "f"(hi));
    return r;
}
__device__ __forceinline__ float sum2(u64 a) {
    float lo, hi;
    asm("mov.b64 {%0, %1}, %2;" : "=f"(lo), "=f"(hi) : "l"(a));
    return lo + hi;
}

// ------------------------------------------------------------------
// Phase 1: dists = l2norm(qk) @ means^T, best-cluster loss accumulate
// (kept bit-identical to the passing version: routing indices are
//  discrete; do not re-roll top-k boundary ties)
// ------------------------------------------------------------------
__global__ void __launch_bounds__(128) k_dists(const float* __restrict__ qk,
                                               const float* __restrict__ means)
{
    __shared__ float sM[Cc * Dd];
    __shared__ float sMsq[Cc];
    __shared__ float sRed[128];

    const int bh  = blockIdx.y;
    const int h   = bh & (Hh - 1);
    const int tid = threadIdx.x;
    const int tok = blockIdx.x * 128 + tid;

    {
        const float4* src = (const float4*)(means + (size_t)h * Cc * Dd);
        float4* dst = (float4*)sM;
        for (int g = tid; g < Cc * Dd / 4; g += 128) dst[g] = src[g];
    }
    __syncthreads();
    if (tid < Cc) {
        float s = 0.f;
        const float* r = sM + tid * Dd;
        #pragma unroll
        for (int d = 0; d < Dd; d++) s = fmaf(r[d], r[d], s);
        sMsq[tid] = s;
    }
    __syncthreads();

    float4 r[16];
    const float4* qrow = (const float4*)(qk + ((size_t)bh * Tt + tok) * Dd);
    #pragma unroll
    for (int i = 0; i < 16; i++) r[i] = qrow[i];
    float nsq = 0.f;
    #pragma unroll
    for (int i = 0; i < 16; i++)
        nsq += r[i].x * r[i].x + r[i].y * r[i].y + r[i].z * r[i].z + r[i].w * r[i].w;
    const float inv = 1.0f / fmaxf(sqrtf(nsq), 1e-12f);
    #pragma unroll
    for (int i = 0; i < 16; i++) {
        r[i].x *= inv; r[i].y *= inv; r[i].z *= inv; r[i].w *= inv;
    }

    float best = -3.402823e38f;
    int   bc   = 0;
    float* drow = g_dists + (size_t)bh * Cc * Tt + tok;

    #pragma unroll 2
    for (int c = 0; c < Cc; c++) {
        const float4* m4 = (const float4*)(sM + c * Dd);
        float a0 = 0.f, a1 = 0.f, a2 = 0.f, a3 = 0.f;
        #pragma unroll
        for (int i = 0; i < 16; i++) {
            float4 m = m4[i];
            a0 = fmaf(r[i].x, m.x, a0);
            a1 = fmaf(r[i].y, m.y, a1);
            a2 = fmaf(r[i].z, m.z, a2);
            a3 = fmaf(r[i].w, m.w, a3);
        }
        float dist = (a0 + a1) + (a2 + a3);
        drow[(size_t)c * Tt] = dist;
        if (dist > best) { best = dist; bc = c; }
    }

    sRed[tid] = nsq * inv * inv - 2.0f * best + sMsq[bc];
    __syncthreads();
    for (int s = 64; s > 0; s >>= 1) {
        if (tid < s) sRed[tid] += sRed[tid + s];
        __syncthreads();
    }
    if (tid == 0) atomicAdd(&g_loss, (double)sRed[0]);
}

// ------------------------------------------------------------------
// Phase 2: exact top-128 per row, ascending-index output (unchanged)
// ------------------------------------------------------------------
__global__ void __launch_bounds__(256) k_topk()
{
    __shared__ unsigned sk[Tt];
    __shared__ unsigned hist[256];
    __shared__ unsigned sg[256];
    __shared__ unsigned se[256];
    __shared__ unsigned s_pivot;
    __shared__ int      s_need;

    const int row = blockIdx.x;
    const int tid = threadIdx.x;
    const float* src = g_dists + (size_t)row * Tt;

    for (int i = tid; i < Tt; i += 256) {
        unsigned u = __float_as_uint(src[i]);
        u ^= (u & 0x80000000u) ? 0xFFFFFFFFu : 0x80000000u;
        sk[i] = u;
    }

    unsigned prefix = 0;
    int remaining = Ww;
    for (int pass = 0; pass < 4; pass++) {
        const int shift = 24 - pass * 8;
        const unsigned himask = (pass == 0) ? 0u : (0xFFFFFFFFu << (shift + 8));
        hist[tid] = 0;
        __syncthreads();
        for (int i = tid; i < Tt; i += 256) {
            unsigned u = sk[i];
            if ((u & himask) == prefix) atomicAdd(&hist[(u >> shift) & 255], 1u);
        }
        __syncthreads();
        if (tid == 0) {
            int cum = 0;
            int b = 255;
            for (; b > 0; b--) {
                int cc = (int)hist[b];
                if (cum + cc >= remaining) break;
                cum += cc;
            }
            s_pivot = prefix | ((unsigned)b << shift);
            s_need  = remaining - cum;
        }
        __syncthreads();
        prefix    = s_pivot;
        remaining = s_need;
    }
    const unsigned pivot = prefix;
    const int need_eq = remaining;

    int gt = 0, eq = 0;
    const int base = tid * 32;
    for (int j = 0; j < 32; j++) {
        unsigned u = sk[base + j];
        gt += (u > pivot);
        eq += (u == pivot);
    }
    sg[tid] = (unsigned)gt;
    se[tid] = (unsigned)eq;
    __syncthreads();
    if (tid == 0) {
        unsigned ag = 0, ae = 0;
        for (int i = 0; i < 256; i++) {
            unsigned tg = sg[i], te = se[i];
            sg[i] = ag; se[i] = ae;
            ag += tg; ae += te;
        }
    }
    __syncthreads();

    int gb = (int)sg[tid], eb = (int)se[tid];
    int* outp = g_idx + row * Ww;
    for (int j = 0; j < 32; j++) {
        int e = base + j;
        unsigned u = sk[e];
        if (u > pivot) {
            outp[gb + min(eb, need_eq)] = e;
            gb++;
        } else if (u == pivot) {
            if (eb < need_eq) outp[gb + eb] = e;
            eb++;
        }
    }
}

// ------------------------------------------------------------------
// Phase 3: per-cluster attention with packed f32x2 FMA in all 3 GEMMs
// ------------------------------------------------------------------
__global__ void __launch_bounds__(512, 1) k_attn(const float* __restrict__ qk,
                                                 const float* __restrict__ v,
                                                 const float* __restrict__ relw,
                                                 float* __restrict__ out)
{
    extern __shared__ float sm[];
    float* sQ   = sm;                    // [128][QP]
    float* sV   = sQ + 128 * QP;         // [128][QP]
    float* sB   = sV + 128 * QP;         // [128][QP] rel_w[:,h,:]*scale
    float* sD   = sB + 128 * QP;         // [128][DP]
    float* sInv = sD + 128 * DP;         // 128
    float* sRow = sInv + 128;            // 128
    int*   sIdx = (int*)(sRow + 128);    // 128

    const int blk = blockIdx.x;
    const int bh  = blk >> 6;
    const int h   = bh & (Hh - 1);
    const int tid = threadIdx.x;
    const int l   = tid & 31;
    const int w   = tid >> 5;

    if (tid < 128) sIdx[tid] = g_idx[blk * Ww + tid];
    __syncthreads();

    const float* qkb = qk + (size_t)bh * Tt * Dd;
    const float* vb  = v  + (size_t)bh * Tt * Dd;
    for (int g = tid; g < 128 * 16; g += 512) {
        int r = g >> 4, c4 = (g & 15) << 2;
        int off = sIdx[r] * Dd + c4;
        *(float4*)(sQ + r * QP + c4) = *(const float4*)(qkb + off);
        *(float4*)(sV + r * QP + c4) = *(const float4*)(vb + off);
        float4 rw = *(const float4*)(relw + (r * Hh + h) * Dd + c4);
        rw.x *= 0.125f; rw.y *= 0.125f; rw.z *= 0.125f; rw.w *= 0.125f;
        *(float4*)(sB + r * QP + c4) = rw;
    }
    __syncthreads();
    if (tid < 128) {
        float s = 0.f;
        const float* row = sQ + tid * QP;
        #pragma unroll
        for (int d = 0; d < Dd; d++) s = fmaf(row[d], row[d], s);
        sInv[tid] = 0.125f / fmaxf(sqrtf(s), 1e-12f);
    }
    __syncthreads();

    const int p0 = 8 * w;

    // ---- S[p][q'] = (q_p . q_q') * (scale/||k_q'||), packed over d ----
    {
        u64 acc[8][4];
        #pragma unroll
        for (int i = 0; i < 8; i++)
            #pragma unroll
            for (int j = 0; j < 4; j++) acc[i][j] = 0ull;
        #pragma unroll 1
        for (int dd = 0; dd < Dd; dd += 4) {
            u64 k0[4], k1[4];
            #pragma unroll
            for (int j = 0; j < 4; j++) {
                const float* kp = sQ + (l + 32 * j) * QP + dd;
                k0[j] = *(const u64*)kp;
                k1[j] = *(const u64*)(kp + 2);
            }
            #pragma unroll
            for (int ih = 0; ih < 2; ih++) {
                u64 q0[4], q1[4];
                #pragma unroll
                for (int i = 0; i < 4; i++) {
                    const float* qp = sQ + (p0 + 4 * ih + i) * QP + dd;
                    q0[i] = *(const u64*)qp;
                    q1[i] = *(const u64*)(qp + 2);
                }
                #pragma unroll
                for (int i = 0; i < 4; i++)
                    #pragma unroll
                    for (int j = 0; j < 4; j++) {
                        ffma2(acc[4 * ih + i][j], q0[i], k0[j]);
                        ffma2(acc[4 * ih + i][j], q1[i], k1[j]);
                    }
            }
        }
        #pragma unroll
        for (int j = 0; j < 4; j++) {
            float sc = sInv[l + 32 * j];
            #pragma unroll
            for (int i = 0; i < 8; i++)
                sD[(p0 + i) * DP + (l + 32 * j)] = sum2(acc[i][j]) * sc;
        }
    }
    __syncwarp();

    // ---- R[p][r] = q_p . relw_r ; fold _shift, packed over d ----
    {
        u64 acc[8][4];
        #pragma unroll
        for (int i = 0; i < 8; i++)
            #pragma unroll
            for (int j = 0; j < 4; j++) acc[i][j] = 0ull;
        #pragma unroll 1
        for (int dd = 0; dd < Dd; dd += 4) {
            u64 b0[4], b1[4];
            #pragma unroll
            for (int j = 0; j < 4; j++) {
                const float* bp = sB + (l + 32 * j) * QP + dd;
                b0[j] = *(const u64*)bp;
                b1[j] = *(const u64*)(bp + 2);
            }
            #pragma unroll
            for (int ih = 0; ih < 2; ih++) {
                u64 q0[4], q1[4];
                #pragma unroll
                for (int i = 0; i < 4; i++) {
                    const float* qp = sQ + (p0 + 4 * ih + i) * QP + dd;
                    q0[i] = *(const u64*)qp;
                    q1[i] = *(const u64*)(qp + 2);
                }
                #pragma unroll
                for (int i = 0; i < 4; i++)
                    #pragma unroll
                    for (int j = 0; j < 4; j++) {
                        ffma2(acc[4 * ih + i][j], q0[i], b0[j]);
                        ffma2(acc[4 * ih + i][j], q1[i], b1[j]);
                    }
            }
        }
        #pragma unroll
        for (int i = 0; i < 8; i++) {
            int p = p0 + i;
            #pragma unroll
            for (int j = 0; j < 4; j++) {
                int qc = p + (l + 32 * j) - 127;
                if (qc >= 0) sD[p * DP + qc] += sum2(acc[i][j]);
            }
        }
    }
    __syncwarp();
    if (l < 8) sD[(p0 + l) * DP + (p0 + l)] = -50000.0f;
    __syncwarp();

    // ---- softmax per row (warp-local) ----
    #pragma unroll
    for (int i = 0; i < 8; i++) {
        int p = p0 + i;
        float vv[4];
        float mx = -3.402823e38f;
        #pragma unroll
        for (int j = 0; j < 4; j++) {
            vv[j] = sD[p * DP + l + 32 * j];
            mx = fmaxf(mx, vv[j]);
        }
        #pragma unroll
        for (int o = 16; o > 0; o >>= 1) mx = fmaxf(mx, __shfl_xor_sync(0xffffffffu, mx, o));
        float s = 0.f;
        #pragma unroll
        for (int j = 0; j < 4; j++) {
            vv[j] = expf(vv[j] - mx);
            s += vv[j];
            sD[p * DP + l + 32 * j] = vv[j];
        }
        #pragma unroll
        for (int o = 16; o > 0; o >>= 1) s += __shfl_xor_sync(0xffffffffu, s, o);
        if (l == 0) sRow[p] = 1.0f / s;
    }
    __syncwarp();

    // ---- O = attn @ v, packed over j-pairs; atomic scatter ----
    {
        u64 accx[8], accy[8];
        #pragma unroll
        for (int i = 0; i < 8; i++) { accx[i] = 0ull; accy[i] = 0ull; }
        #pragma unroll 2
        for (int j = 0; j < 128; j += 2) {
            float2 vf0 = *(const float2*)(sV + j * QP + 2 * l);
            float2 vf1 = *(const float2*)(sV + (j + 1) * QP + 2 * l);
            u64 vx = packf2(vf0.x, vf1.x);
            u64 vy = packf2(vf0.y, vf1.y);
            #pragma unroll
            for (int i = 0; i < 8; i++) {
                u64 a2 = *(const u64*)(sD + (p0 + i) * DP + j);
                ffma2(accx[i], a2, vx);
                ffma2(accy[i], a2, vy);
            }
        }
        #pragma unroll
        for (int i = 0; i < 8; i++) {
            int p = p0 + i;
            float rinv = sRow[p];
            float* dst = out + ((size_t)bh * Tt + sIdx[p]) * Dd + 2 * l;
            atomicAdd(dst,     sum2(accx[i]) * rinv);
            atomicAdd(dst + 1, sum2(accy[i]) * rinv);
        }
        if (l < 8) atomicAdd(&g_cnt[bh * Tt + sIdx[p0 + l]], 1.0f);
    }
}

// ------------------------------------------------------------------
// Phase 4: out = num / (count + eps); append loss scalar (unchanged)
// ------------------------------------------------------------------
__global__ void __launch_bounds__(256) k_final(float* __restrict__ out, int out_size)
{
    int i = blockIdx.x * blockDim.x + threadIdx.x;
    if (i < NOUT / 4) {
        float c  = g_cnt[i >> 4];
        float rs = 1.0f / (c + 1e-5f);
        float4* p = (float4*)out + i;
        float4 vv = *p;
        vv.x *= rs; vv.y *= rs; vv.z *= rs; vv.w *= rs;
        *p = vv;
    }
    if (i == 0 && out_size > NOUT) {
        out[NOUT] = (float)(g_loss * (1.0e-4 / (double)NOUT));
    }
}

extern "C" void kernel_launch(void* const* d_in, const int* in_sizes, int n_in,
                              void* d_out, int out_size)
{
    const float* qk    = (const float*)d_in[0];
    const float* v     = (const float*)d_in[1];
    const float* means = (const float*)d_in[2];
    const float* relw  = (const float*)d_in[3];
    float* out = (float*)d_out;

    cudaMemsetAsync(d_out, 0, (size_t)out_size * sizeof(float));
    void* cp = 0; cudaGetSymbolAddress(&cp, g_cnt);
    cudaMemsetAsync(cp, 0, (size_t)BH * Tt * sizeof(float));
    void* lp = 0; cudaGetSymbolAddress(&lp, g_loss);
    cudaMemsetAsync(lp, 0, sizeof(double));

    dim3 g1(Tt / 128, BH);
    k_dists<<<g1, 128>>>(qk, means);

    k_topk<<<NROW, 256>>>();

    const int smem_attn = (128 * QP * 3 + 128 * DP + 128 + 128 + 128) * 4;
    cudaFuncSetAttribute(k_attn, cudaFuncAttributeMaxDynamicSharedMemorySize, smem_attn);
    k_attn<<<NROW, 512, smem_attn>>>(qk, v, relw, out);

    k_final<<<NOUT / 4 / 256, 256>>>(out, out_size);
}

// round 8
// speedup vs baseline: 1.1835x; 1.1835x over previous
#include <cuda_runtime.h>
#include <math.h>

#define Bb   4
#define Hh   8
#define Tt   8192
#define Dd   64
#define Cc   64
#define Ww   128
#define BH   (Bb*Hh)
#define NROW (BH*Cc)
#define NOUT (BH*Tt*Dd)
#define QP 68
#define DP 132

__device__ float  g_dists[(size_t)NROW * Tt];
__device__ int    g_idx[NROW * Ww];
__device__ float  g_cnt[BH * Tt];
__device__ double g_loss;

// ---- tf32 helpers ------------------------------------------------
__device__ __forceinline__ unsigned f2tf(float x) {
    unsigned r;
    asm("cvt.rna.tf32.f32 %0, %1;" : "=r"(r) : "f"(x));
    return r;
}
__device__ __forceinline__ void split_tf(float x, unsigned &hi, unsigned &lo) {
    asm("cvt.rna.tf32.f32 %0, %1;" : "=r"(hi) : "f"(x));
    float res = x - __uint_as_float(hi);
    asm("cvt.rna.tf32.f32 %0, %1;" : "=r"(lo) : "f"(res));
}
// D += A(16x8) * B(8x8), tf32 inputs, f32 accum
__device__ __forceinline__ void mma8(float* c, const unsigned* a, const unsigned* b) {
    asm("mma.sync.aligned.m16n8k8.row.col.f32.tf32.tf32.f32 "
        "{%0,%1,%2,%3}, {%4,%5,%6,%7}, {%8,%9}, {%0,%1,%2,%3};"
        : "+f"(c[0]), "+f"(c[1]), "+f"(c[2]), "+f"(c[3])
        : "r"(a[0]), "r"(a[1]), "r"(a[2]), "r"(a[3]), "r"(b[0]), "r"(b[1]));
}

// ------------------------------------------------------------------
// Phase 1: dists = l2norm(qk) @ means^T (bit-identical to passing ver)
// ------------------------------------------------------------------
__global__ void __launch_bounds__(128) k_dists(const float* __restrict__ qk,
                                               const float* __restrict__ means)
{
    __shared__ float sM[Cc * Dd];
    __shared__ float sMsq[Cc];
    __shared__ float sRed[128];

    const int bh  = blockIdx.y;
    const int h   = bh & (Hh - 1);
    const int tid = threadIdx.x;
    const int tok = blockIdx.x * 128 + tid;

    {
        const float4* src = (const float4*)(means + (size_t)h * Cc * Dd);
        float4* dst = (float4*)sM;
        for (int g = tid; g < Cc * Dd / 4; g += 128) dst[g] = src[g];
    }
    __syncthreads();
    if (tid < Cc) {
        float s = 0.f;
        const float* r = sM + tid * Dd;
        #pragma unroll
        for (int d = 0; d < Dd; d++) s = fmaf(r[d], r[d], s);
        sMsq[tid] = s;
    }
    __syncthreads();

    float4 r[16];
    const float4* qrow = (const float4*)(qk + ((size_t)bh * Tt + tok) * Dd);
    #pragma unroll
    for (int i = 0; i < 16; i++) r[i] = qrow[i];
    float nsq = 0.f;
    #pragma unroll
    for (int i = 0; i < 16; i++)
        nsq += r[i].x * r[i].x + r[i].y * r[i].y + r[i].z * r[i].z + r[i].w * r[i].w;
    const float inv = 1.0f / fmaxf(sqrtf(nsq), 1e-12f);
    #pragma unroll
    for (int i = 0; i < 16; i++) {
        r[i].x *= inv; r[i].y *= inv; r[i].z *= inv; r[i].w *= inv;
    }

    float best = -3.402823e38f;
    int   bc   = 0;
    float* drow = g_dists + (size_t)bh * Cc * Tt + tok;

    #pragma unroll 2
    for (int c = 0; c < Cc; c++) {
        const float4* m4 = (const float4*)(sM + c * Dd);
        float a0 = 0.f, a1 = 0.f, a2 = 0.f, a3 = 0.f;
        #pragma unroll
        for (int i = 0; i < 16; i++) {
            float4 m = m4[i];
            a0 = fmaf(r[i].x, m.x, a0);
            a1 = fmaf(r[i].y, m.y, a1);
            a2 = fmaf(r[i].z, m.z, a2);
            a3 = fmaf(r[i].w, m.w, a3);
        }
        float dist = (a0 + a1) + (a2 + a3);
        drow[(size_t)c * Tt] = dist;
        if (dist > best) { best = dist; bc = c; }
    }

    sRed[tid] = nsq * inv * inv - 2.0f * best + sMsq[bc];
    __syncthreads();
    for (int s = 64; s > 0; s >>= 1) {
        if (tid < s) sRed[tid] += sRed[tid + s];
        __syncthreads();
    }
    if (tid == 0) atomicAdd(&g_loss, (double)sRed[0]);
}

// ------------------------------------------------------------------
// Phase 2: exact top-128 per row, ascending-index output (unchanged)
// ------------------------------------------------------------------
__global__ void __launch_bounds__(256) k_topk()
{
    __shared__ unsigned sk[Tt];
    __shared__ unsigned hist[256];
    __shared__ unsigned sg[256];
    __shared__ unsigned se[256];
    __shared__ unsigned s_pivot;
    __shared__ int      s_need;

    const int row = blockIdx.x;
    const int tid = threadIdx.x;
    const float* src = g_dists + (size_t)row * Tt;

    for (int i = tid; i < Tt; i += 256) {
        unsigned u = __float_as_uint(src[i]);
        u ^= (u & 0x80000000u) ? 0xFFFFFFFFu : 0x80000000u;
        sk[i] = u;
    }

    unsigned prefix = 0;
    int remaining = Ww;
    for (int pass = 0; pass < 4; pass++) {
        const int shift = 24 - pass * 8;
        const unsigned himask = (pass == 0) ? 0u : (0xFFFFFFFFu << (shift + 8));
        hist[tid] = 0;
        __syncthreads();
        for (int i = tid; i < Tt; i += 256) {
            unsigned u = sk[i];
            if ((u & himask) == prefix) atomicAdd(&hist[(u >> shift) & 255], 1u);
        }
        __syncthreads();
        if (tid == 0) {
            int cum = 0;
            int b = 255;
            for (; b > 0; b--) {
                int cc = (int)hist[b];
                if (cum + cc >= remaining) break;
                cum += cc;
            }
            s_pivot = prefix | ((unsigned)b << shift);
            s_need  = remaining - cum;
        }
        __syncthreads();
        prefix    = s_pivot;
        remaining = s_need;
    }
    const unsigned pivot = prefix;
    const int need_eq = remaining;

    int gt = 0, eq = 0;
    const int base = tid * 32;
    for (int j = 0; j < 32; j++) {
        unsigned u = sk[base + j];
        gt += (u > pivot);
        eq += (u == pivot);
    }
    sg[tid] = (unsigned)gt;
    se[tid] = (unsigned)eq;
    __syncthreads();
    if (tid == 0) {
        unsigned ag = 0, ae = 0;
        for (int i = 0; i < 256; i++) {
            unsigned tg = sg[i], te = se[i];
            sg[i] = ag; se[i] = ae;
            ag += tg; ae += te;
        }
    }
    __syncthreads();

    int gb = (int)sg[tid], eb = (int)se[tid];
    int* outp = g_idx + row * Ww;
    for (int j = 0; j < 32; j++) {
        int e = base + j;
        unsigned u = sk[e];
        if (u > pivot) {
            outp[gb + min(eb, need_eq)] = e;
            gb++;
        } else if (u == pivot) {
            if (eb < need_eq) outp[gb + eb] = e;
            eb++;
        }
    }
}

// ------------------------------------------------------------------
// Phase 3: per-cluster attention on tensor cores (mma.sync tf32)
// ------------------------------------------------------------------
__global__ void __launch_bounds__(512, 1) k_attn(const float* __restrict__ qk,
                                                 const float* __restrict__ v,
                                                 const float* __restrict__ relw,
                                                 float* __restrict__ out)
{
    extern __shared__ float sm[];
    float* sQ   = sm;                    // [128][QP]
    float* sV   = sQ + 128 * QP;         // [128][QP]
    float* sB   = sV + 128 * QP;         // [128][QP] rel_w[:,h,:]*scale
    float* sD   = sB + 128 * QP;         // [128][DP]
    float* sInv = sD + 128 * DP;         // 128
    float* sRow = sInv + 128;            // 128
    int*   sIdx = (int*)(sRow + 128);    // 128

    const int blk = blockIdx.x;
    const int bh  = blk >> 6;
    const int h   = bh & (Hh - 1);
    const int tid = threadIdx.x;
    const int l   = tid & 31;
    const int w   = tid >> 5;
    const int g   = l >> 2;   // 0..7 (mma group)
    const int t   = l & 3;    // 0..3 (thread in group)

    if (tid < 128) sIdx[tid] = g_idx[blk * Ww + tid];
    __syncthreads();

    const float* qkb = qk + (size_t)bh * Tt * Dd;
    const float* vb  = v  + (size_t)bh * Tt * Dd;
    for (int gg = tid; gg < 128 * 16; gg += 512) {
        int r = gg >> 4, c4 = (gg & 15) << 2;
        int off = sIdx[r] * Dd + c4;
        *(float4*)(sQ + r * QP + c4) = *(const float4*)(qkb + off);
        *(float4*)(sV + r * QP + c4) = *(const float4*)(vb + off);
        float4 rw = *(const float4*)(relw + (r * Hh + h) * Dd + c4);
        rw.x *= 0.125f; rw.y *= 0.125f; rw.z *= 0.125f; rw.w *= 0.125f;
        *(float4*)(sB + r * QP + c4) = rw;
    }
    __syncthreads();
    if (tid < 128) {
        float s = 0.f;
        const float* row = sQ + tid * QP;
        #pragma unroll
        for (int d = 0; d < Dd; d++) s = fmaf(row[d], row[d], s);
        sInv[tid] = 0.125f / fmaxf(sqrtf(s), 1e-12f);
    }
    __syncthreads();

    const int wm = w >> 2, wn = w & 3;    // 4x4 grid of 32x32 tiles (S, R)

    // ---- S = Q.Q^T (3xTF32), column-scaled by sInv ----
    {
        float acc[2][4][4];
        #pragma unroll
        for (int mt = 0; mt < 2; mt++)
            #pragma unroll
            for (int nt = 0; nt < 4; nt++)
                #pragma unroll
                for (int q = 0; q < 4; q++) acc[mt][nt][q] = 0.f;

        #pragma unroll 1
        for (int kt = 0; kt < 8; kt++) {
            const int k0 = kt * 8;
            unsigned ahi[2][4], alo[2][4];
            #pragma unroll
            for (int mt = 0; mt < 2; mt++) {
                const float* ap = sQ + (32 * wm + 16 * mt + g) * QP + k0 + t;
                split_tf(ap[0],          ahi[mt][0], alo[mt][0]);
                split_tf(ap[8 * QP],     ahi[mt][1], alo[mt][1]);
                split_tf(ap[4],          ahi[mt][2], alo[mt][2]);
                split_tf(ap[8 * QP + 4], ahi[mt][3], alo[mt][3]);
            }
            unsigned bhi[4][2], blo[4][2];
            #pragma unroll
            for (int nt = 0; nt < 4; nt++) {
                const float* bp = sQ + (32 * wn + 8 * nt + g) * QP + k0 + t;
                split_tf(bp[0], bhi[nt][0], blo[nt][0]);
                split_tf(bp[4], bhi[nt][1], blo[nt][1]);
            }
            #pragma unroll
            for (int mt = 0; mt < 2; mt++)
                #pragma unroll
                for (int nt = 0; nt < 4; nt++) {
                    mma8(acc[mt][nt], ahi[mt], bhi[nt]);
                    mma8(acc[mt][nt], ahi[mt], blo[nt]);
                    mma8(acc[mt][nt], alo[mt], bhi[nt]);
                }
        }
        #pragma unroll
        for (int mt = 0; mt < 2; mt++)
            #pragma unroll
            for (int nt = 0; nt < 4; nt++) {
                int row = 32 * wm + 16 * mt + g;
                int col = 32 * wn + 8 * nt + 2 * t;
                float s0 = sInv[col], s1 = sInv[col + 1];
                sD[row * DP + col]           = acc[mt][nt][0] * s0;
                sD[row * DP + col + 1]       = acc[mt][nt][1] * s1;
                sD[(row + 8) * DP + col]     = acc[mt][nt][2] * s0;
                sD[(row + 8) * DP + col + 1] = acc[mt][nt][3] * s1;
            }
    }
    __syncthreads();

    // ---- R = Q.relw^T (single tf32 pass), _shift folded; tiles wm+wn>=3 only ----
    if (wm + wn >= 3) {
        float acc[2][4][4];
        #pragma unroll
        for (int mt = 0; mt < 2; mt++)
            #pragma unroll
            for (int nt = 0; nt < 4; nt++)
                #pragma unroll
                for (int q = 0; q < 4; q++) acc[mt][nt][q] = 0.f;

        #pragma unroll 1
        for (int kt = 0; kt < 8; kt++) {
            const int k0 = kt * 8;
            unsigned ah[2][4];
            #pragma unroll
            for (int mt = 0; mt < 2; mt++) {
                const float* ap = sQ + (32 * wm + 16 * mt + g) * QP + k0 + t;
                ah[mt][0] = f2tf(ap[0]);
                ah[mt][1] = f2tf(ap[8 * QP]);
                ah[mt][2] = f2tf(ap[4]);
                ah[mt][3] = f2tf(ap[8 * QP + 4]);
            }
            unsigned bh_[4][2];
            #pragma unroll
            for (int nt = 0; nt < 4; nt++) {
                const float* bp = sB + (32 * wn + 8 * nt + g) * QP + k0 + t;
                bh_[nt][0] = f2tf(bp[0]);
                bh_[nt][1] = f2tf(bp[4]);
            }
            #pragma unroll
            for (int mt = 0; mt < 2; mt++)
                #pragma unroll
                for (int nt = 0; nt < 4; nt++)
                    mma8(acc[mt][nt], ah[mt], bh_[nt]);
        }
        #pragma unroll
        for (int mt = 0; mt < 2; mt++)
            #pragma unroll
            for (int nt = 0; nt < 4; nt++) {
                int p0r = 32 * wm + 16 * mt + g;
                int col = 32 * wn + 8 * nt + 2 * t;
                int qc0 = p0r + col - 127;
                if (qc0 >= 0)     sD[p0r * DP + qc0]           += acc[mt][nt][0];
                if (qc0 + 1 >= 0) sD[p0r * DP + qc0 + 1]       += acc[mt][nt][1];
                int qc2 = p0r + 8 + col - 127;
                if (qc2 >= 0)     sD[(p0r + 8) * DP + qc2]     += acc[mt][nt][2];
                if (qc2 + 1 >= 0) sD[(p0r + 8) * DP + qc2 + 1] += acc[mt][nt][3];
            }
    }
    __syncthreads();

    // ---- diag mask + softmax: warp w owns rows 8w..8w+7 ----
    const int p0 = 8 * w;
    if (l < 8) sD[(p0 + l) * DP + (p0 + l)] = -50000.0f;
    __syncwarp();
    #pragma unroll
    for (int i = 0; i < 8; i++) {
        int p = p0 + i;
        float vv[4];
        float mx = -3.402823e38f;
        #pragma unroll
        for (int j = 0; j < 4; j++) {
            vv[j] = sD[p * DP + l + 32 * j];
            mx = fmaxf(mx, vv[j]);
        }
        #pragma unroll
        for (int o = 16; o > 0; o >>= 1) mx = fmaxf(mx, __shfl_xor_sync(0xffffffffu, mx, o));
        float s = 0.f;
        #pragma unroll
        for (int j = 0; j < 4; j++) {
            vv[j] = expf(vv[j] - mx);
            s += vv[j];
            sD[p * DP + l + 32 * j] = vv[j];
        }
        #pragma unroll
        for (int o = 16; o > 0; o >>= 1) s += __shfl_xor_sync(0xffffffffu, s, o);
        if (l == 0) sRow[p] = 1.0f / s;
    }
    if (l < 8) atomicAdd(&g_cnt[bh * Tt + sIdx[p0 + l]], 1.0f);
    __syncthreads();

    // ---- O = attn.V (3xTF32), row-normalized, atomic scatter ----
    {
        const int om = w >> 1, on = w & 1;    // 8x2 grid of 16x32 tiles
        float acc[4][4];
        #pragma unroll
        for (int nt = 0; nt < 4; nt++)
            #pragma unroll
            for (int q = 0; q < 4; q++) acc[nt][q] = 0.f;

        #pragma unroll 1
        for (int kt = 0; kt < 16; kt++) {
            const int k0 = kt * 8;
            unsigned ahi[4], alo[4];
            const float* ap = sD + (16 * om + g) * DP + k0 + t;
            split_tf(ap[0],          ahi[0], alo[0]);
            split_tf(ap[8 * DP],     ahi[1], alo[1]);
            split_tf(ap[4],          ahi[2], alo[2]);
            split_tf(ap[8 * DP + 4], ahi[3], alo[3]);
            unsigned bhi[4][2], blo[4][2];
            #pragma unroll
            for (int nt = 0; nt < 4; nt++) {
                int col = 32 * on + 8 * nt + g;
                split_tf(sV[(k0 + t) * QP + col],     bhi[nt][0], blo[nt][0]);
                split_tf(sV[(k0 + t + 4) * QP + col], bhi[nt][1], blo[nt][1]);
            }
            #pragma unroll
            for (int nt = 0; nt < 4; nt++) {
                mma8(acc[nt], ahi, bhi[nt]);
                mma8(acc[nt], ahi, blo[nt]);
                mma8(acc[nt], alo, bhi[nt]);
            }
        }
        int row = 16 * om + g;
        float r0 = sRow[row], r1 = sRow[row + 8];
        float* d0 = out + ((size_t)bh * Tt + sIdx[row]) * Dd;
        float* d1 = out + ((size_t)bh * Tt + sIdx[row + 8]) * Dd;
        #pragma unroll
        for (int nt = 0; nt < 4; nt++) {
            int col = 32 * on + 8 * nt + 2 * t;
            atomicAdd(d0 + col,     acc[nt][0] * r0);
            atomicAdd(d0 + col + 1, acc[nt][1] * r0);
            atomicAdd(d1 + col,     acc[nt][2] * r1);
            atomicAdd(d1 + col + 1, acc[nt][3] * r1);
        }
    }
}

// ------------------------------------------------------------------
// Phase 4: out = num / (count + eps); append loss scalar (unchanged)
// ------------------------------------------------------------------
__global__ void __launch_bounds__(256) k_final(float* __restrict__ out, int out_size)
{
    int i = blockIdx.x * blockDim.x + threadIdx.x;
    if (i < NOUT / 4) {
        float c  = g_cnt[i >> 4];
        float rs = 1.0f / (c + 1e-5f);
        float4* p = (float4*)out + i;
        float4 vv = *p;
        vv.x *= rs; vv.y *= rs; vv.z *= rs; vv.w *= rs;
        *p = vv;
    }
    if (i == 0 && out_size > NOUT) {
        out[NOUT] = (float)(g_loss * (1.0e-4 / (double)NOUT));
    }
}

extern "C" void kernel_launch(void* const* d_in, const int* in_sizes, int n_in,
                              void* d_out, int out_size)
{
    const float* qk    = (const float*)d_in[0];
    const float* v     = (const float*)d_in[1];
    const float* means = (const float*)d_in[2];
    const float* relw  = (const float*)d_in[3];
    float* out = (float*)d_out;

    cudaMemsetAsync(d_out, 0, (size_t)out_size * sizeof(float));
    void* cp = 0; cudaGetSymbolAddress(&cp, g_cnt);
    cudaMemsetAsync(cp, 0, (size_t)BH * Tt * sizeof(float));
    void* lp = 0; cudaGetSymbolAddress(&lp, g_loss);
    cudaMemsetAsync(lp, 0, sizeof(double));

    dim3 g1(Tt / 128, BH);
    k_dists<<<g1, 128>>>(qk, means);

    k_topk<<<NROW, 256>>>();

    const int smem_attn = (128 * QP * 3 + 128 * DP + 128 + 128 + 128) * 4;
    cudaFuncSetAttribute(k_attn, cudaFuncAttributeMaxDynamicSharedMemorySize, smem_attn);
    k_attn<<<NROW, 512, smem_attn>>>(qk, v, relw, out);

    k_final<<<NOUT / 4 / 256, 256>>>(out, out_size);
}

// round 9
// speedup vs baseline: 1.2206x; 1.0314x over previous
#include <cuda_runtime.h>
#include <math.h>

#define Bb   4
#define Hh   8
#define Tt   8192
#define Dd   64
#define Cc   64
#define Ww   128
#define BH   (Bb*Hh)
#define NROW (BH*Cc)
#define NOUT (BH*Tt*Dd)
#define QP 68
#define DP 132

__device__ float  g_dists[(size_t)NROW * Tt];
__device__ int    g_idx[NROW * Ww];
__device__ float  g_cnt[BH * Tt];
__device__ double g_loss;

// ---- tf32 helpers ------------------------------------------------
__device__ __forceinline__ unsigned f2tf(float x) {
    unsigned r;
    asm("cvt.rna.tf32.f32 %0, %1;" : "=r"(r) : "f"(x));
    return r;
}
__device__ __forceinline__ void split_tf(float x, unsigned &hi, unsigned &lo) {
    asm("cvt.rna.tf32.f32 %0, %1;" : "=r"(hi) : "f"(x));
    float res = x - __uint_as_float(hi);
    asm("cvt.rna.tf32.f32 %0, %1;" : "=r"(lo) : "f"(res));
}
__device__ __forceinline__ void mma8(float* c, const unsigned* a, const unsigned* b) {
    asm("mma.sync.aligned.m16n8k8.row.col.f32.tf32.tf32.f32 "
        "{%0,%1,%2,%3}, {%4,%5,%6,%7}, {%8,%9}, {%0,%1,%2,%3};"
        : "+f"(c[0]), "+f"(c[1]), "+f"(c[2]), "+f"(c[3])
        : "r"(a[0]), "r"(a[1]), "r"(a[2]), "r"(a[3]), "r"(b[0]), "r"(b[1]));
}
#define FB(x) __float_as_uint(x)

// ------------------------------------------------------------------
// Phase 1: dists = l2norm(qk) @ means^T (bit-identical, do not touch)
// ------------------------------------------------------------------
__global__ void __launch_bounds__(128) k_dists(const float* __restrict__ qk,
                                               const float* __restrict__ means)
{
    __shared__ float sM[Cc * Dd];
    __shared__ float sMsq[Cc];
    __shared__ float sRed[128];

    const int bh  = blockIdx.y;
    const int h   = bh & (Hh - 1);
    const int tid = threadIdx.x;
    const int tok = blockIdx.x * 128 + tid;

    {
        const float4* src = (const float4*)(means + (size_t)h * Cc * Dd);
        float4* dst = (float4*)sM;
        for (int g = tid; g < Cc * Dd / 4; g += 128) dst[g] = src[g];
    }
    __syncthreads();
    if (tid < Cc) {
        float s = 0.f;
        const float* r = sM + tid * Dd;
        #pragma unroll
        for (int d = 0; d < Dd; d++) s = fmaf(r[d], r[d], s);
        sMsq[tid] = s;
    }
    __syncthreads();

    float4 r[16];
    const float4* qrow = (const float4*)(qk + ((size_t)bh * Tt + tok) * Dd);
    #pragma unroll
    for (int i = 0; i < 16; i++) r[i] = qrow[i];
    float nsq = 0.f;
    #pragma unroll
    for (int i = 0; i < 16; i++)
        nsq += r[i].x * r[i].x + r[i].y * r[i].y + r[i].z * r[i].z + r[i].w * r[i].w;
    const float inv = 1.0f / fmaxf(sqrtf(nsq), 1e-12f);
    #pragma unroll
    for (int i = 0; i < 16; i++) {
        r[i].x *= inv; r[i].y *= inv; r[i].z *= inv; r[i].w *= inv;
    }

    float best = -3.402823e38f;
    int   bc   = 0;
    float* drow = g_dists + (size_t)bh * Cc * Tt + tok;

    #pragma unroll 2
    for (int c = 0; c < Cc; c++) {
        const float4* m4 = (const float4*)(sM + c * Dd);
        float a0 = 0.f, a1 = 0.f, a2 = 0.f, a3 = 0.f;
        #pragma unroll
        for (int i = 0; i < 16; i++) {
            float4 m = m4[i];
            a0 = fmaf(r[i].x, m.x, a0);
            a1 = fmaf(r[i].y, m.y, a1);
            a2 = fmaf(r[i].z, m.z, a2);
            a3 = fmaf(r[i].w, m.w, a3);
        }
        float dist = (a0 + a1) + (a2 + a3);
        drow[(size_t)c * Tt] = dist;
        if (dist > best) { best = dist; bc = c; }
    }

    sRed[tid] = nsq * inv * inv - 2.0f * best + sMsq[bc];
    __syncthreads();
    for (int s = 64; s > 0; s >>= 1) {
        if (tid < s) sRed[tid] += sRed[tid + s];
        __syncthreads();
    }
    if (tid == 0) atomicAdd(&g_loss, (double)sRed[0]);
}

// ------------------------------------------------------------------
// Phase 2: exact top-128 per row. Same selection, parallelized:
// warp-aggregated histogram atomics + parallel suffix-scan pivot +
// two-level shfl scan for the ordered emission.
// ------------------------------------------------------------------
__global__ void __launch_bounds__(256) k_topk()
{
    __shared__ unsigned sk[Tt];
    __shared__ unsigned hist[256];
    __shared__ unsigned warpagg[8];
    __shared__ unsigned warpbase[8];
    __shared__ unsigned s_pivot;
    __shared__ int      s_need;

    const int row = blockIdx.x;
    const int tid = threadIdx.x;
    const int lane = tid & 31;
    const int wrp  = tid >> 5;
    const float* src = g_dists + (size_t)row * Tt;

    for (int i = tid; i < Tt; i += 256) {
        unsigned u = __float_as_uint(src[i]);
        u ^= (u & 0x80000000u) ? 0xFFFFFFFFu : 0x80000000u;
        sk[i] = u;
    }

    unsigned prefix = 0;
    int remaining = Ww;
    for (int pass = 0; pass < 4; pass++) {
        const int shift = 24 - pass * 8;
        const unsigned himask = (pass == 0) ? 0u : (0xFFFFFFFFu << (shift + 8));
        hist[tid] = 0;
        __syncthreads();
        for (int i = tid; i < Tt; i += 256) {
            unsigned u = sk[i];
            bool act = ((u & himask) == prefix);
            unsigned am = __ballot_sync(0xFFFFFFFFu, act);
            if (act) {
                int bin = (u >> shift) & 255;
                unsigned m = __match_any_sync(am, bin);
                if (lane == __ffs(m) - 1)
                    atomicAdd(&hist[bin], (unsigned)__popc(m));
            }
        }
        __syncthreads();
        // inclusive suffix sums of hist
        #pragma unroll
        for (int off = 1; off < 256; off <<= 1) {
            unsigned vc = hist[tid] + ((tid + off < 256) ? hist[tid + off] : 0u);
            __syncthreads();
            hist[tid] = vc;
            __syncthreads();
        }
        unsigned sb = hist[tid];
        unsigned sn = (tid == 255) ? 0u : hist[tid + 1];
        if (sb >= (unsigned)remaining && sn < (unsigned)remaining) {
            s_pivot = prefix | ((unsigned)tid << shift);
            s_need  = remaining - (int)sn;
        }
        __syncthreads();
        prefix    = s_pivot;
        remaining = s_need;
        __syncthreads();
    }
    const unsigned pivot = prefix;
    const int need_eq = remaining;

    int gt = 0, eq = 0;
    const int base = tid * 32;
    for (int j = 0; j < 32; j++) {
        unsigned u = sk[base + j];
        gt += (u > pivot);
        eq += (u == pivot);
    }
    // two-level exclusive scan of packed (gt<<16)|eq
    unsigned pk = ((unsigned)gt << 16) | (unsigned)eq;
    unsigned x = pk;
    #pragma unroll
    for (int o = 1; o < 32; o <<= 1) {
        unsigned y = __shfl_up_sync(0xFFFFFFFFu, x, o);
        if (lane >= o) x += y;
    }
    if (lane == 31) warpagg[wrp] = x;
    __syncthreads();
    if (tid == 0) {
        unsigned a = 0;
        for (int i = 0; i < 8; i++) { unsigned t0 = warpagg[i]; warpbase[i] = a; a += t0; }
    }
    __syncthreads();
    unsigned excl = x - pk + warpbase[wrp];
    int gb = (int)(excl >> 16);
    int eb = (int)(excl & 0xFFFFu);

    int* outp = g_idx + row * Ww;
    for (int j = 0; j < 32; j++) {
        int e = base + j;
        unsigned u = sk[e];
        if (u > pivot) {
            outp[gb + min(eb, need_eq)] = e;
            gb++;
        } else if (u == pivot) {
            if (eb < need_eq) outp[gb + eb] = e;
            eb++;
        }
    }
}

// ------------------------------------------------------------------
// Phase 3: tensor-core attention, all splits precomputed (no cvt in
// the mma loops). SMEM region lifetime plan (floats, QP=68, DP=132):
//   A [0      ,  8704): Qhi            -> Vlo   (after R)
//   B [8704   , 17408): Qlo            -> attn-lo rows (stride DP)
//   C [17408  , 26112): relw tf32      -> attn-lo overflow
//   E [26112  , 34816): V raw          -> Vhi (in-place split)
//   D [34816  , 51712): scores/attn-hi (stride DP)
// ------------------------------------------------------------------
__global__ void __launch_bounds__(512, 1) k_attn(const float* __restrict__ qk,
                                                 const float* __restrict__ v,
                                                 const float* __restrict__ relw,
                                                 float* __restrict__ out)
{
    extern __shared__ float sm[];
    float* sA   = sm;                    // Qhi -> Vlo
    float* sB   = sm + 8704;             // Qlo -> attn-lo (stride DP)
    float* sC   = sm + 17408;            // relw tf32
    float* sE   = sm + 26112;            // Vraw -> Vhi
    float* sD   = sm + 34816;            // scores, stride DP
    float* sInv = sm + 51712;
    float* sRow = sInv + 128;
    int*   sIdx = (int*)(sRow + 128);
    float* sL   = sB;                    // attn-lo overlay (stride DP)

    const int blk = blockIdx.x;
    const int bh  = blk >> 6;
    const int h   = bh & (Hh - 1);
    const int tid = threadIdx.x;
    const int l   = tid & 31;
    const int w   = tid >> 5;
    const int g   = l >> 2;
    const int t   = l & 3;

    if (tid < 128) sIdx[tid] = g_idx[blk * Ww + tid];
    __syncthreads();

    const float* qkb = qk + (size_t)bh * Tt * Dd;
    const float* vb  = v  + (size_t)bh * Tt * Dd;
    for (int gg = tid; gg < 128 * 16; gg += 512) {
        int r = gg >> 4, c4 = (gg & 15) << 2;
        int off = sIdx[r] * Dd + c4;
        float4 q = *(const float4*)(qkb + off);
        float4 qh, ql;
        unsigned hi, lo;
        split_tf(q.x, hi, lo); qh.x = __uint_as_float(hi); ql.x = __uint_as_float(lo);
        split_tf(q.y, hi, lo); qh.y = __uint_as_float(hi); ql.y = __uint_as_float(lo);
        split_tf(q.z, hi, lo); qh.z = __uint_as_float(hi); ql.z = __uint_as_float(lo);
        split_tf(q.w, hi, lo); qh.w = __uint_as_float(hi); ql.w = __uint_as_float(lo);
        *(float4*)(sA + r * QP + c4) = qh;
        *(float4*)(sB + r * QP + c4) = ql;
        *(float4*)(sE + r * QP + c4) = *(const float4*)(vb + off);
        float4 rw = *(const float4*)(relw + (r * Hh + h) * Dd + c4);
        rw.x = __uint_as_float(f2tf(rw.x * 0.125f));
        rw.y = __uint_as_float(f2tf(rw.y * 0.125f));
        rw.z = __uint_as_float(f2tf(rw.z * 0.125f));
        rw.w = __uint_as_float(f2tf(rw.w * 0.125f));
        *(float4*)(sC + r * QP + c4) = rw;
    }
    __syncthreads();
    if (tid < 128) {
        float s = 0.f;
        const float* rh = sA + tid * QP;
        const float* rl = sB + tid * QP;
        #pragma unroll
        for (int d = 0; d < Dd; d++) {
            float q = rh[d] + rl[d];
            s = fmaf(q, q, s);
        }
        sInv[tid] = 0.125f / fmaxf(sqrtf(s), 1e-12f);
    }
    __syncthreads();

    const int wm = w >> 2, wn = w & 3;

    // ---- S = Q.Q^T (3xTF32, pre-split operands) ----
    {
        float acc[2][4][4];
        #pragma unroll
        for (int mt = 0; mt < 2; mt++)
            #pragma unroll
            for (int nt = 0; nt < 4; nt++)
                #pragma unroll
                for (int q = 0; q < 4; q++) acc[mt][nt][q] = 0.f;

        #pragma unroll 1
        for (int kt = 0; kt < 8; kt++) {
            const int k0 = kt * 8;
            unsigned ahi[2][4], alo[2][4];
            #pragma unroll
            for (int mt = 0; mt < 2; mt++) {
                const int ro = (32 * wm + 16 * mt + g) * QP + k0 + t;
                ahi[mt][0] = FB(sA[ro]);              alo[mt][0] = FB(sB[ro]);
                ahi[mt][1] = FB(sA[ro + 8 * QP]);     alo[mt][1] = FB(sB[ro + 8 * QP]);
                ahi[mt][2] = FB(sA[ro + 4]);          alo[mt][2] = FB(sB[ro + 4]);
                ahi[mt][3] = FB(sA[ro + 8 * QP + 4]); alo[mt][3] = FB(sB[ro + 8 * QP + 4]);
            }
            unsigned bhi[4][2], blo[4][2];
            #pragma unroll
            for (int nt = 0; nt < 4; nt++) {
                const int ro = (32 * wn + 8 * nt + g) * QP + k0 + t;
                bhi[nt][0] = FB(sA[ro]);     blo[nt][0] = FB(sB[ro]);
                bhi[nt][1] = FB(sA[ro + 4]); blo[nt][1] = FB(sB[ro + 4]);
            }
            #pragma unroll
            for (int mt = 0; mt < 2; mt++)
                #pragma unroll
                for (int nt = 0; nt < 4; nt++) {
                    mma8(acc[mt][nt], ahi[mt], bhi[nt]);
                    mma8(acc[mt][nt], ahi[mt], blo[nt]);
                    mma8(acc[mt][nt], alo[mt], bhi[nt]);
                }
        }
        #pragma unroll
        for (int mt = 0; mt < 2; mt++)
            #pragma unroll
            for (int nt = 0; nt < 4; nt++) {
                int row = 32 * wm + 16 * mt + g;
                int col = 32 * wn + 8 * nt + 2 * t;
                float s0 = sInv[col], s1 = sInv[col + 1];
                sD[row * DP + col]           = acc[mt][nt][0] * s0;
                sD[row * DP + col + 1]       = acc[mt][nt][1] * s1;
                sD[(row + 8) * DP + col]     = acc[mt][nt][2] * s0;
                sD[(row + 8) * DP + col + 1] = acc[mt][nt][3] * s1;
            }
    }
    __syncthreads();

    // ---- R = Q.relw^T (tf32 hi only), _shift folded; tiles wm+wn>=3 ----
    if (wm + wn >= 3) {
        float acc[2][4][4];
        #pragma unroll
        for (int mt = 0; mt < 2; mt++)
            #pragma unroll
            for (int nt = 0; nt < 4; nt++)
                #pragma unroll
                for (int q = 0; q < 4; q++) acc[mt][nt][q] = 0.f;

        #pragma unroll 1
        for (int kt = 0; kt < 8; kt++) {
            const int k0 = kt * 8;
            unsigned ah[2][4];
            #pragma unroll
            for (int mt = 0; mt < 2; mt++) {
                const int ro = (32 * wm + 16 * mt + g) * QP + k0 + t;
                ah[mt][0] = FB(sA[ro]);
                ah[mt][1] = FB(sA[ro + 8 * QP]);
                ah[mt][2] = FB(sA[ro + 4]);
                ah[mt][3] = FB(sA[ro + 8 * QP + 4]);
            }
            unsigned bh_[4][2];
            #pragma unroll
            for (int nt = 0; nt < 4; nt++) {
                const int ro = (32 * wn + 8 * nt + g) * QP + k0 + t;
                bh_[nt][0] = FB(sC[ro]);
                bh_[nt][1] = FB(sC[ro + 4]);
            }
            #pragma unroll
            for (int mt = 0; mt < 2; mt++)
                #pragma unroll
                for (int nt = 0; nt < 4; nt++)
                    mma8(acc[mt][nt], ah[mt], bh_[nt]);
        }
        #pragma unroll
        for (int mt = 0; mt < 2; mt++)
            #pragma unroll
            for (int nt = 0; nt < 4; nt++) {
                int p0r = 32 * wm + 16 * mt + g;
                int col = 32 * wn + 8 * nt + 2 * t;
                int qc0 = p0r + col - 127;
                if (qc0 >= 0)     sD[p0r * DP + qc0]           += acc[mt][nt][0];
                if (qc0 + 1 >= 0) sD[p0r * DP + qc0 + 1]       += acc[mt][nt][1];
                int qc2 = p0r + 8 + col - 127;
                if (qc2 >= 0)     sD[(p0r + 8) * DP + qc2]     += acc[mt][nt][2];
                if (qc2 + 1 >= 0) sD[(p0r + 8) * DP + qc2 + 1] += acc[mt][nt][3];
            }
    }
    __syncthreads();

    // ---- V split (E->hi in place, lo->A) ; diag mask + softmax with
    //      pre-split exp written to sD (hi) and sL (lo) ----
    for (int gg = tid; gg < 128 * 16; gg += 512) {
        int r = gg >> 4, c4 = (gg & 15) << 2;
        float4 vv = *(float4*)(sE + r * QP + c4);
        float4 vh, vl;
        unsigned hi, lo;
        split_tf(vv.x, hi, lo); vh.x = __uint_as_float(hi); vl.x = __uint_as_float(lo);
        split_tf(vv.y, hi, lo); vh.y = __uint_as_float(hi); vl.y = __uint_as_float(lo);
        split_tf(vv.z, hi, lo); vh.z = __uint_as_float(hi); vl.z = __uint_as_float(lo);
        split_tf(vv.w, hi, lo); vh.w = __uint_as_float(hi); vl.w = __uint_as_float(lo);
        *(float4*)(sE + r * QP + c4) = vh;
        *(float4*)(sA + r * QP + c4) = vl;
    }
    const int p0 = 8 * w;
    if (l < 8) sD[(p0 + l) * DP + (p0 + l)] = -50000.0f;
    __syncwarp();
    #pragma unroll
    for (int i = 0; i < 8; i++) {
        int p = p0 + i;
        float vv[4];
        float mx = -3.402823e38f;
        #pragma unroll
        for (int j = 0; j < 4; j++) {
            vv[j] = sD[p * DP + l + 32 * j];
            mx = fmaxf(mx, vv[j]);
        }
        #pragma unroll
        for (int o = 16; o > 0; o >>= 1) mx = fmaxf(mx, __shfl_xor_sync(0xffffffffu, mx, o));
        float s = 0.f;
        #pragma unroll
        for (int j = 0; j < 4; j++) {
            vv[j] = expf(vv[j] - mx);
            s += vv[j];
            unsigned hi, lo;
            split_tf(vv[j], hi, lo);
            sD[p * DP + l + 32 * j] = __uint_as_float(hi);
            sL[p * DP + l + 32 * j] = __uint_as_float(lo);
        }
        #pragma unroll
        for (int o = 16; o > 0; o >>= 1) s += __shfl_xor_sync(0xffffffffu, s, o);
        if (l == 0) sRow[p] = 1.0f / s;
    }
    if (l < 8) atomicAdd(&g_cnt[bh * Tt + sIdx[p0 + l]], 1.0f);
    __syncthreads();

    // ---- O = attn.V (3xTF32, pre-split operands), scatter ----
    {
        const int om = w >> 1, on = w & 1;
        float acc[4][4];
        #pragma unroll
        for (int nt = 0; nt < 4; nt++)
            #pragma unroll
            for (int q = 0; q < 4; q++) acc[nt][q] = 0.f;

        #pragma unroll 1
        for (int kt = 0; kt < 16; kt++) {
            const int k0 = kt * 8;
            unsigned ahi[4], alo[4];
            const int ro = (16 * om + g) * DP + k0 + t;
            ahi[0] = FB(sD[ro]);              alo[0] = FB(sL[ro]);
            ahi[1] = FB(sD[ro + 8 * DP]);     alo[1] = FB(sL[ro + 8 * DP]);
            ahi[2] = FB(sD[ro + 4]);          alo[2] = FB(sL[ro + 4]);
            ahi[3] = FB(sD[ro + 8 * DP + 4]); alo[3] = FB(sL[ro + 8 * DP + 4]);
            unsigned bhi[4][2], blo[4][2];
            #pragma unroll
            for (int nt = 0; nt < 4; nt++) {
                int col = 32 * on + 8 * nt + g;
                bhi[nt][0] = FB(sE[(k0 + t) * QP + col]);     blo[nt][0] = FB(sA[(k0 + t) * QP + col]);
                bhi[nt][1] = FB(sE[(k0 + t + 4) * QP + col]); blo[nt][1] = FB(sA[(k0 + t + 4) * QP + col]);
            }
            #pragma unroll
            for (int nt = 0; nt < 4; nt++) {
                mma8(acc[nt], ahi, bhi[nt]);
                mma8(acc[nt], ahi, blo[nt]);
                mma8(acc[nt], alo, bhi[nt]);
            }
        }
        int row = 16 * om + g;
        float r0 = sRow[row], r1 = sRow[row + 8];
        float* d0 = out + ((size_t)bh * Tt + sIdx[row]) * Dd;
        float* d1 = out + ((size_t)bh * Tt + sIdx[row + 8]) * Dd;
        #pragma unroll
        for (int nt = 0; nt < 4; nt++) {
            int col = 32 * on + 8 * nt + 2 * t;
            atomicAdd(d0 + col,     acc[nt][0] * r0);
            atomicAdd(d0 + col + 1, acc[nt][1] * r0);
            atomicAdd(d1 + col,     acc[nt][2] * r1);
            atomicAdd(d1 + col + 1, acc[nt][3] * r1);
        }
    }
}

// ------------------------------------------------------------------
// Phase 4: out = num / (count + eps); append loss scalar (unchanged)
// ------------------------------------------------------------------
__global__ void __launch_bounds__(256) k_final(float* __restrict__ out, int out_size)
{
    int i = blockIdx.x * blockDim.x + threadIdx.x;
    if (i < NOUT / 4) {
        float c  = g_cnt[i >> 4];
        float rs = 1.0f / (c + 1e-5f);
        float4* p = (float4*)out + i;
        float4 vv = *p;
        vv.x *= rs; vv.y *= rs; vv.z *= rs; vv.w *= rs;
        *p = vv;
    }
    if (i == 0 && out_size > NOUT) {
        out[NOUT] = (float)(g_loss * (1.0e-4 / (double)NOUT));
    }
}

extern "C" void kernel_launch(void* const* d_in, const int* in_sizes, int n_in,
                              void* d_out, int out_size)
{
    const float* qk    = (const float*)d_in[0];
    const float* v     = (const float*)d_in[1];
    const float* means = (const float*)d_in[2];
    const float* relw  = (const float*)d_in[3];
    float* out = (float*)d_out;

    cudaMemsetAsync(d_out, 0, (size_t)out_size * sizeof(float));
    void* cp = 0; cudaGetSymbolAddress(&cp, g_cnt);
    cudaMemsetAsync(cp, 0, (size_t)BH * Tt * sizeof(float));
    void* lp = 0; cudaGetSymbolAddress(&lp, g_loss);
    cudaMemsetAsync(lp, 0, sizeof(double));

    dim3 g1(Tt / 128, BH);
    k_dists<<<g1, 128>>>(qk, means);

    k_topk<<<NROW, 256>>>();

    const int smem_attn = (51712 + 128 + 128 + 128) * 4;   // 208,384 B
    cudaFuncSetAttribute(k_attn, cudaFuncAttributeMaxDynamicSharedMemorySize, smem_attn);
    k_attn<<<NROW, 512, smem_attn>>>(qk, v, relw, out);

    k_final<<<NOUT / 4 / 256, 256>>>(out, out_size);
}

// round 11
// speedup vs baseline: 1.2607x; 1.0328x over previous
#include <cuda_runtime.h>
#include <math.h>

#define Bb   4
#define Hh   8
#define Tt   8192
#define Dd   64
#define Cc   64
#define Ww   128
#define BH   (Bb*Hh)
#define NROW (BH*Cc)
#define NOUT (BH*Tt*Dd)
#define QP 68
#define DP 132

__device__ float  g_dists[(size_t)NROW * Tt];
__device__ int    g_idx[NROW * Ww];
__device__ float  g_cnt[BH * Tt];
__device__ double g_loss;

// ---- tf32 helpers ------------------------------------------------
__device__ __forceinline__ unsigned f2tf(float x) {
    unsigned r;
    asm("cvt.rna.tf32.f32 %0, %1;" : "=r"(r) : "f"(x));
    return r;
}
__device__ __forceinline__ void split_tf(float x, unsigned &hi, unsigned &lo) {
    asm("cvt.rna.tf32.f32 %0, %1;" : "=r"(hi) : "f"(x));
    float res = x - __uint_as_float(hi);
    asm("cvt.rna.tf32.f32 %0, %1;" : "=r"(lo) : "f"(res));
}
__device__ __forceinline__ void mma8(float* c, const unsigned* a, const unsigned* b) {
    asm("mma.sync.aligned.m16n8k8.row.col.f32.tf32.tf32.f32 "
        "{%0,%1,%2,%3}, {%4,%5,%6,%7}, {%8,%9}, {%0,%1,%2,%3};"
        : "+f"(c[0]), "+f"(c[1]), "+f"(c[2]), "+f"(c[3])
        : "r"(a[0]), "r"(a[1]), "r"(a[2]), "r"(a[3]), "r"(b[0]), "r"(b[1]));
}
#define FB(x) __float_as_uint(x)

// ------------------------------------------------------------------
// Phase 1: dists = l2norm(qk) @ means^T (bit-identical, do not touch)
// ------------------------------------------------------------------
__global__ void __launch_bounds__(128) k_dists(const float* __restrict__ qk,
                                               const float* __restrict__ means)
{
    __shared__ float sM[Cc * Dd];
    __shared__ float sMsq[Cc];
    __shared__ float sRed[128];

    const int bh  = blockIdx.y;
    const int h   = bh & (Hh - 1);
    const int tid = threadIdx.x;
    const int tok = blockIdx.x * 128 + tid;

    {
        const float4* src = (const float4*)(means + (size_t)h * Cc * Dd);
        float4* dst = (float4*)sM;
        for (int g = tid; g < Cc * Dd / 4; g += 128) dst[g] = src[g];
    }
    __syncthreads();
    if (tid < Cc) {
        float s = 0.f;
        const float* r = sM + tid * Dd;
        #pragma unroll
        for (int d = 0; d < Dd; d++) s = fmaf(r[d], r[d], s);
        sMsq[tid] = s;
    }
    __syncthreads();

    float4 r[16];
    const float4* qrow = (const float4*)(qk + ((size_t)bh * Tt + tok) * Dd);
    #pragma unroll
    for (int i = 0; i < 16; i++) r[i] = qrow[i];
    float nsq = 0.f;
    #pragma unroll
    for (int i = 0; i < 16; i++)
        nsq += r[i].x * r[i].x + r[i].y * r[i].y + r[i].z * r[i].z + r[i].w * r[i].w;
    const float inv = 1.0f / fmaxf(sqrtf(nsq), 1e-12f);
    #pragma unroll
    for (int i = 0; i < 16; i++) {
        r[i].x *= inv; r[i].y *= inv; r[i].z *= inv; r[i].w *= inv;
    }

    float best = -3.402823e38f;
    int   bc   = 0;
    float* drow = g_dists + (size_t)bh * Cc * Tt + tok;

    #pragma unroll 2
    for (int c = 0; c < Cc; c++) {
        const float4* m4 = (const float4*)(sM + c * Dd);
        float a0 = 0.f, a1 = 0.f, a2 = 0.f, a3 = 0.f;
        #pragma unroll
        for (int i = 0; i < 16; i++) {
            float4 m = m4[i];
            a0 = fmaf(r[i].x, m.x, a0);
            a1 = fmaf(r[i].y, m.y, a1);
            a2 = fmaf(r[i].z, m.z, a2);
            a3 = fmaf(r[i].w, m.w, a3);
        }
        float dist = (a0 + a1) + (a2 + a3);
        drow[(size_t)c * Tt] = dist;
        if (dist > best) { best = dist; bc = c; }
    }

    sRed[tid] = nsq * inv * inv - 2.0f * best + sMsq[bc];
    __syncthreads();
    for (int s = 64; s > 0; s >>= 1) {
        if (tid < s) sRed[tid] += sRed[tid + s];
        __syncthreads();
    }
    if (tid == 0) atomicAdd(&g_loss, (double)sRed[0]);
}

// ------------------------------------------------------------------
// Phase 2: exact top-128 per row (unchanged from R9)
// ------------------------------------------------------------------
__global__ void __launch_bounds__(256) k_topk()
{
    __shared__ unsigned sk[Tt];
    __shared__ unsigned hist[256];
    __shared__ unsigned warpagg[8];
    __shared__ unsigned warpbase[8];
    __shared__ unsigned s_pivot;
    __shared__ int      s_need;

    const int row = blockIdx.x;
    const int tid = threadIdx.x;
    const int lane = tid & 31;
    const int wrp  = tid >> 5;
    const float* src = g_dists + (size_t)row * Tt;

    for (int i = tid; i < Tt; i += 256) {
        unsigned u = __float_as_uint(src[i]);
        u ^= (u & 0x80000000u) ? 0xFFFFFFFFu : 0x80000000u;
        sk[i] = u;
    }

    unsigned prefix = 0;
    int remaining = Ww;
    for (int pass = 0; pass < 4; pass++) {
        const int shift = 24 - pass * 8;
        const unsigned himask = (pass == 0) ? 0u : (0xFFFFFFFFu << (shift + 8));
        hist[tid] = 0;
        __syncthreads();
        for (int i = tid; i < Tt; i += 256) {
            unsigned u = sk[i];
            bool act = ((u & himask) == prefix);
            unsigned am = __ballot_sync(0xFFFFFFFFu, act);
            if (act) {
                int bin = (u >> shift) & 255;
                unsigned m = __match_any_sync(am, bin);
                if (lane == __ffs(m) - 1)
                    atomicAdd(&hist[bin], (unsigned)__popc(m));
            }
        }
        __syncthreads();
        #pragma unroll
        for (int off = 1; off < 256; off <<= 1) {
            unsigned vc = hist[tid] + ((tid + off < 256) ? hist[tid + off] : 0u);
            __syncthreads();
            hist[tid] = vc;
            __syncthreads();
        }
        unsigned sb = hist[tid];
        unsigned sn = (tid == 255) ? 0u : hist[tid + 1];
        if (sb >= (unsigned)remaining && sn < (unsigned)remaining) {
            s_pivot = prefix | ((unsigned)tid << shift);
            s_need  = remaining - (int)sn;
        }
        __syncthreads();
        prefix    = s_pivot;
        remaining = s_need;
        __syncthreads();
    }
    const unsigned pivot = prefix;
    const int need_eq = remaining;

    int gt = 0, eq = 0;
    const int base = tid * 32;
    for (int j = 0; j < 32; j++) {
        unsigned u = sk[base + j];
        gt += (u > pivot);
        eq += (u == pivot);
    }
    unsigned pk = ((unsigned)gt << 16) | (unsigned)eq;
    unsigned x = pk;
    #pragma unroll
    for (int o = 1; o < 32; o <<= 1) {
        unsigned y = __shfl_up_sync(0xFFFFFFFFu, x, o);
        if (lane >= o) x += y;
    }
    if (lane == 31) warpagg[wrp] = x;
    __syncthreads();
    if (tid == 0) {
        unsigned a = 0;
        for (int i = 0; i < 8; i++) { unsigned t0 = warpagg[i]; warpbase[i] = a; a += t0; }
    }
    __syncthreads();
    unsigned excl = x - pk + warpbase[wrp];
    int gb = (int)(excl >> 16);
    int eb = (int)(excl & 0xFFFFu);

    int* outp = g_idx + row * Ww;
    for (int j = 0; j < 32; j++) {
        int e = base + j;
        unsigned u = sk[e];
        if (u > pivot) {
            outp[gb + min(eb, need_eq)] = e;
            gb++;
        } else if (u == pivot) {
            if (eb < need_eq) outp[gb + eb] = e;
            eb++;
        }
    }
}

// ------------------------------------------------------------------
// Phase 3: tensor-core attention; R10 = latency-hiding pass
//   A [0      ,  8704): Qhi            -> Vlo   (after R)
//   B [8704   , 17408): Qlo            -> attn-lo rows (stride DP)
//   C [17408  , 26112): relw tf32      -> attn-lo overflow
//   E [26112  , 34816): V raw          -> Vhi (in-place split)
//   D [34816  , 51712): scores/attn-hi (stride DP)
// ------------------------------------------------------------------
__global__ void __launch_bounds__(512, 1) k_attn(const float* __restrict__ qk,
                                                 const float* __restrict__ v,
                                                 const float* __restrict__ relw,
                                                 float* __restrict__ out)
{
    extern __shared__ float sm[];
    float* sA   = sm;
    float* sB   = sm + 8704;
    float* sC   = sm + 17408;
    float* sE   = sm + 26112;
    float* sD   = sm + 34816;
    float* sInv = sm + 51712;
    float* sRow = sInv + 128;
    int*   sIdx = (int*)(sRow + 128);
    float* sL   = sB;

    const int blk = blockIdx.x;
    const int bh  = blk >> 6;
    const int h   = bh & (Hh - 1);
    const int tid = threadIdx.x;
    const int l   = tid & 31;
    const int w   = tid >> 5;
    const int g   = l >> 2;
    const int t   = l & 3;

    if (tid < 128) sIdx[tid] = g_idx[blk * Ww + tid];
    __syncthreads();

    const float* qkb = qk + (size_t)bh * Tt * Dd;
    const float* vb  = v  + (size_t)bh * Tt * Dd;
    // gather: all 12 LDG.128 issued up front (full unroll -> max MLP)
    {
        float4 qv[4], vv[4], rw[4];
        int ro[4], co[4];
        #pragma unroll
        for (int it = 0; it < 4; it++) {
            int gg = tid + it * 512;
            int r = gg >> 4, c4 = (gg & 15) << 2;
            ro[it] = r; co[it] = c4;
            int off = sIdx[r] * Dd + c4;
            qv[it] = *(const float4*)(qkb + off);
            vv[it] = *(const float4*)(vb + off);
            rw[it] = *(const float4*)(relw + (r * Hh + h) * Dd + c4);
        }
        #pragma unroll
        for (int it = 0; it < 4; it++) {
            float4 qh, ql;
            unsigned hi, lo;
            split_tf(qv[it].x, hi, lo); qh.x = __uint_as_float(hi); ql.x = __uint_as_float(lo);
            split_tf(qv[it].y, hi, lo); qh.y = __uint_as_float(hi); ql.y = __uint_as_float(lo);
            split_tf(qv[it].z, hi, lo); qh.z = __uint_as_float(hi); ql.z = __uint_as_float(lo);
            split_tf(qv[it].w, hi, lo); qh.w = __uint_as_float(hi); ql.w = __uint_as_float(lo);
            *(float4*)(sA + ro[it] * QP + co[it]) = qh;
            *(float4*)(sB + ro[it] * QP + co[it]) = ql;
            *(float4*)(sE + ro[it] * QP + co[it]) = vv[it];
            float4 rr = rw[it];
            rr.x = __uint_as_float(f2tf(rr.x * 0.125f));
            rr.y = __uint_as_float(f2tf(rr.y * 0.125f));
            rr.z = __uint_as_float(f2tf(rr.z * 0.125f));
            rr.w = __uint_as_float(f2tf(rr.w * 0.125f));
            *(float4*)(sC + ro[it] * QP + co[it]) = rr;
        }
    }
    __syncthreads();
    if (tid < 128) {
        float s = 0.f;
        const float* rh = sA + tid * QP;
        const float* rl = sB + tid * QP;
        #pragma unroll
        for (int d = 0; d < Dd; d++) {
            float q = rh[d] + rl[d];
            s = fmaf(q, q, s);
        }
        sInv[tid] = 0.125f / fmaxf(sqrtf(s), 1e-12f);
    }
    __syncthreads();

    const int wm = w >> 2, wn = w & 3;

    // ---- S = Q.Q^T (3xTF32), software-pipelined kt ----
    {
        float acc[2][4][4];
        #pragma unroll
        for (int mt = 0; mt < 2; mt++)
            #pragma unroll
            for (int nt = 0; nt < 4; nt++)
                #pragma unroll
                for (int q = 0; q < 4; q++) acc[mt][nt][q] = 0.f;

        #pragma unroll 2
        for (int kt = 0; kt < 8; kt++) {
            const int k0 = kt * 8;
            unsigned ahi[2][4], alo[2][4];
            #pragma unroll
            for (int mt = 0; mt < 2; mt++) {
                const int ro = (32 * wm + 16 * mt + g) * QP + k0 + t;
                ahi[mt][0] = FB(sA[ro]);              alo[mt][0] = FB(sB[ro]);
                ahi[mt][1] = FB(sA[ro + 8 * QP]);     alo[mt][1] = FB(sB[ro + 8 * QP]);
                ahi[mt][2] = FB(sA[ro + 4]);          alo[mt][2] = FB(sB[ro + 4]);
                ahi[mt][3] = FB(sA[ro + 8 * QP + 4]); alo[mt][3] = FB(sB[ro + 8 * QP + 4]);
            }
            unsigned bhi[4][2], blo[4][2];
            #pragma unroll
            for (int nt = 0; nt < 4; nt++) {
                const int ro = (32 * wn + 8 * nt + g) * QP + k0 + t;
                bhi[nt][0] = FB(sA[ro]);     blo[nt][0] = FB(sB[ro]);
                bhi[nt][1] = FB(sA[ro + 4]); blo[nt][1] = FB(sB[ro + 4]);
            }
            #pragma unroll
            for (int mt = 0; mt < 2; mt++)
                #pragma unroll
                for (int nt = 0; nt < 4; nt++) {
                    mma8(acc[mt][nt], ahi[mt], bhi[nt]);
                    mma8(acc[mt][nt], ahi[mt], blo[nt]);
                    mma8(acc[mt][nt], alo[mt], bhi[nt]);
                }
        }
        #pragma unroll
        for (int mt = 0; mt < 2; mt++)
            #pragma unroll
            for (int nt = 0; nt < 4; nt++) {
                int row = 32 * wm + 16 * mt + g;
                int col = 32 * wn + 8 * nt + 2 * t;
                float s0 = sInv[col], s1 = sInv[col + 1];
                sD[row * DP + col]           = acc[mt][nt][0] * s0;
                sD[row * DP + col + 1]       = acc[mt][nt][1] * s1;
                sD[(row + 8) * DP + col]     = acc[mt][nt][2] * s0;
                sD[(row + 8) * DP + col + 1] = acc[mt][nt][3] * s1;
            }
    }
    __syncthreads();

    // ---- R = Q.relw^T (tf32 hi only), _shift folded; tiles wm+wn>=3 ----
    if (wm + wn >= 3) {
        float acc[2][4][4];
        #pragma unroll
        for (int mt = 0; mt < 2; mt++)
            #pragma unroll
            for (int nt = 0; nt < 4; nt++)
                #pragma unroll
                for (int q = 0; q < 4; q++) acc[mt][nt][q] = 0.f;

        #pragma unroll 2
        for (int kt = 0; kt < 8; kt++) {
            const int k0 = kt * 8;
            unsigned ah[2][4];
            #pragma unroll
            for (int mt = 0; mt < 2; mt++) {
                const int ro = (32 * wm + 16 * mt + g) * QP + k0 + t;
                ah[mt][0] = FB(sA[ro]);
                ah[mt][1] = FB(sA[ro + 8 * QP]);
                ah[mt][2] = FB(sA[ro + 4]);
                ah[mt][3] = FB(sA[ro + 8 * QP + 4]);
            }
            unsigned bh_[4][2];
            #pragma unroll
            for (int nt = 0; nt < 4; nt++) {
                const int ro = (32 * wn + 8 * nt + g) * QP + k0 + t;
                bh_[nt][0] = FB(sC[ro]);
                bh_[nt][1] = FB(sC[ro + 4]);
            }
            #pragma unroll
            for (int mt = 0; mt < 2; mt++)
                #pragma unroll
                for (int nt = 0; nt < 4; nt++)
                    mma8(acc[mt][nt], ah[mt], bh_[nt]);
        }
        #pragma unroll
        for (int mt = 0; mt < 2; mt++)
            #pragma unroll
            for (int nt = 0; nt < 4; nt++) {
                int p0r = 32 * wm + 16 * mt + g;
                int col = 32 * wn + 8 * nt + 2 * t;
                int qc0 = p0r + col - 127;
                if (qc0 >= 0)     sD[p0r * DP + qc0]           += acc[mt][nt][0];
                if (qc0 + 1 >= 0) sD[p0r * DP + qc0 + 1]       += acc[mt][nt][1];
                int qc2 = p0r + 8 + col - 127;
                if (qc2 >= 0)     sD[(p0r + 8) * DP + qc2]     += acc[mt][nt][2];
                if (qc2 + 1 >= 0) sD[(p0r + 8) * DP + qc2 + 1] += acc[mt][nt][3];
            }
    }
    __syncthreads();

    // ---- V split (E->hi in place, lo->A), max MLP ----
    {
        float4 vv[4];
        int ro[4], co[4];
        #pragma unroll
        for (int it = 0; it < 4; it++) {
            int gg = tid + it * 512;
            int r = gg >> 4, c4 = (gg & 15) << 2;
            ro[it] = r; co[it] = c4;
            vv[it] = *(float4*)(sE + r * QP + c4);
        }
        #pragma unroll
        for (int it = 0; it < 4; it++) {
            float4 vh, vl;
            unsigned hi, lo;
            split_tf(vv[it].x, hi, lo); vh.x = __uint_as_float(hi); vl.x = __uint_as_float(lo);
            split_tf(vv[it].y, hi, lo); vh.y = __uint_as_float(hi); vl.y = __uint_as_float(lo);
            split_tf(vv[it].z, hi, lo); vh.z = __uint_as_float(hi); vl.z = __uint_as_float(lo);
            split_tf(vv[it].w, hi, lo); vh.w = __uint_as_float(hi); vl.w = __uint_as_float(lo);
            *(float4*)(sE + ro[it] * QP + co[it]) = vh;
            *(float4*)(sA + ro[it] * QP + co[it]) = vl;
        }
    }
    const int p0 = 8 * w;
    if (l < 8) sD[(p0 + l) * DP + (p0 + l)] = -50000.0f;
    __syncwarp();
    #pragma unroll
    for (int i = 0; i < 8; i++) {
        int p = p0 + i;
        float vv[4];
        float mx = -3.402823e38f;
        #pragma unroll
        for (int j = 0; j < 4; j++) {
            vv[j] = sD[p * DP + l + 32 * j];
            mx = fmaxf(mx, vv[j]);
        }
        #pragma unroll
        for (int o = 16; o > 0; o >>= 1) mx = fmaxf(mx, __shfl_xor_sync(0xffffffffu, mx, o));
        float s = 0.f;
        #pragma unroll
        for (int j = 0; j < 4; j++) {
            vv[j] = __expf(vv[j] - mx);
            s += vv[j];
            unsigned hi, lo;
            split_tf(vv[j], hi, lo);
            sD[p * DP + l + 32 * j] = __uint_as_float(hi);
            sL[p * DP + l + 32 * j] = __uint_as_float(lo);
        }
        #pragma unroll
        for (int o = 16; o > 0; o >>= 1) s += __shfl_xor_sync(0xffffffffu, s, o);
        if (l == 0) sRow[p] = 1.0f / s;
    }
    if (l < 8) atomicAdd(&g_cnt[bh * Tt + sIdx[p0 + l]], 1.0f);
    __syncthreads();

    // ---- O = attn.V (3xTF32), software-pipelined kt, scatter ----
    {
        const int om = w >> 1, on = w & 1;
        float acc[4][4];
        #pragma unroll
        for (int nt = 0; nt < 4; nt++)
            #pragma unroll
            for (int q = 0; q < 4; q++) acc[nt][q] = 0.f;

        #pragma unroll 2
        for (int kt = 0; kt < 16; kt++) {
            const int k0 = kt * 8;
            unsigned ahi[4], alo[4];
            const int ro = (16 * om + g) * DP + k0 + t;
            ahi[0] = FB(sD[ro]);              alo[0] = FB(sL[ro]);
            ahi[1] = FB(sD[ro + 8 * DP]);     alo[1] = FB(sL[ro + 8 * DP]);
            ahi[2] = FB(sD[ro + 4]);          alo[2] = FB(sL[ro + 4]);
            ahi[3] = FB(sD[ro + 8 * DP + 4]); alo[3] = FB(sL[ro + 8 * DP + 4]);
            unsigned bhi[4][2], blo[4][2];
            #pragma unroll
            for (int nt = 0; nt < 4; nt++) {
                int col = 32 * on + 8 * nt + g;
                bhi[nt][0] = FB(sE[(k0 + t) * QP + col]);     blo[nt][0] = FB(sA[(k0 + t) * QP + col]);
                bhi[nt][1] = FB(sE[(k0 + t + 4) * QP + col]); blo[nt][1] = FB(sA[(k0 + t + 4) * QP + col]);
            }
            #pragma unroll
            for (int nt = 0; nt < 4; nt++) {
                mma8(acc[nt], ahi, bhi[nt]);
                mma8(acc[nt], ahi, blo[nt]);
                mma8(acc[nt], alo, bhi[nt]);
            }
        }
        int row = 16 * om + g;
        float r0 = sRow[row], r1 = sRow[row + 8];
        float* d0 = out + ((size_t)bh * Tt + sIdx[row]) * Dd;
        float* d1 = out + ((size_t)bh * Tt + sIdx[row + 8]) * Dd;
        #pragma unroll
        for (int nt = 0; nt < 4; nt++) {
            int col = 32 * on + 8 * nt + 2 * t;
            atomicAdd(d0 + col,     acc[nt][0] * r0);
            atomicAdd(d0 + col + 1, acc[nt][1] * r0);
            atomicAdd(d1 + col,     acc[nt][2] * r1);
            atomicAdd(d1 + col + 1, acc[nt][3] * r1);
        }
    }
}

// ------------------------------------------------------------------
// Phase 4: out = num / (count + eps); append loss scalar (unchanged)
// ------------------------------------------------------------------
__global__ void __launch_bounds__(256) k_final(float* __restrict__ out, int out_size)
{
    int i = blockIdx.x * blockDim.x + threadIdx.x;
    if (i < NOUT / 4) {
        float c  = g_cnt[i >> 4];
        float rs = 1.0f / (c + 1e-5f);
        float4* p = (float4*)out + i;
        float4 vv = *p;
        vv.x *= rs; vv.y *= rs; vv.z *= rs; vv.w *= rs;
        *p = vv;
    }
    if (i == 0 && out_size > NOUT) {
        out[NOUT] = (float)(g_loss * (1.0e-4 / (double)NOUT));
    }
}

extern "C" void kernel_launch(void* const* d_in, const int* in_sizes, int n_in,
                              void* d_out, int out_size)
{
    const float* qk    = (const float*)d_in[0];
    const float* v     = (const float*)d_in[1];
    const float* means = (const float*)d_in[2];
    const float* relw  = (const float*)d_in[3];
    float* out = (float*)d_out;

    cudaMemsetAsync(d_out, 0, (size_t)out_size * sizeof(float));
    void* cp = 0; cudaGetSymbolAddress(&cp, g_cnt);
    cudaMemsetAsync(cp, 0, (size_t)BH * Tt * sizeof(float));
    void* lp = 0; cudaGetSymbolAddress(&lp, g_loss);
    cudaMemsetAsync(lp, 0, sizeof(double));

    dim3 g1(Tt / 128, BH);
    k_dists<<<g1, 128>>>(qk, means);

    k_topk<<<NROW, 256>>>();

    const int smem_attn = (51712 + 128 + 128 + 128) * 4;
    cudaFuncSetAttribute(k_attn, cudaFuncAttributeMaxDynamicSharedMemorySize, smem_attn);
    k_attn<<<NROW, 512, smem_attn>>>(qk, v, relw, out);

    k_final<<<NOUT / 4 / 256, 256>>>(out, out_size);
}

// round 12
// speedup vs baseline: 1.2846x; 1.0190x over previous
#include <cuda_runtime.h>
#include <math.h>

#define Bb   4
#define Hh   8
#define Tt   8192
#define Dd   64
#define Cc   64
#define Ww   128
#define BH   (Bb*Hh)
#define NROW (BH*Cc)
#define NOUT (BH*Tt*Dd)
#define QP 68
#define DP 132

__device__ float  g_dists[(size_t)NROW * Tt];
__device__ int    g_idx[NROW * Ww];
__device__ float  g_cnt[BH * Tt];
__device__ double g_loss;

// ---- tf32 helpers ------------------------------------------------
__device__ __forceinline__ unsigned f2tf(float x) {
    unsigned r;
    asm("cvt.rna.tf32.f32 %0, %1;" : "=r"(r) : "f"(x));
    return r;
}
__device__ __forceinline__ void split_tf(float x, unsigned &hi, unsigned &lo) {
    asm("cvt.rna.tf32.f32 %0, %1;" : "=r"(hi) : "f"(x));
    float res = x - __uint_as_float(hi);
    asm("cvt.rna.tf32.f32 %0, %1;" : "=r"(lo) : "f"(res));
}
__device__ __forceinline__ void mma8(float* c, const unsigned* a, const unsigned* b) {
    asm("mma.sync.aligned.m16n8k8.row.col.f32.tf32.tf32.f32 "
        "{%0,%1,%2,%3}, {%4,%5,%6,%7}, {%8,%9}, {%0,%1,%2,%3};"
        : "+f"(c[0]), "+f"(c[1]), "+f"(c[2]), "+f"(c[3])
        : "r"(a[0]), "r"(a[1]), "r"(a[2]), "r"(a[3]), "r"(b[0]), "r"(b[1]));
}
#define FB(x) __float_as_uint(x)

// ------------------------------------------------------------------
// Phase 1: dists = l2norm(qk) @ means^T (bit-identical, do not touch)
// ------------------------------------------------------------------
__global__ void __launch_bounds__(128) k_dists(const float* __restrict__ qk,
                                               const float* __restrict__ means)
{
    __shared__ float sM[Cc * Dd];
    __shared__ float sMsq[Cc];
    __shared__ float sRed[128];

    const int bh  = blockIdx.y;
    const int h   = bh & (Hh - 1);
    const int tid = threadIdx.x;
    const int tok = blockIdx.x * 128 + tid;

    {
        const float4* src = (const float4*)(means + (size_t)h * Cc * Dd);
        float4* dst = (float4*)sM;
        for (int g = tid; g < Cc * Dd / 4; g += 128) dst[g] = src[g];
    }
    __syncthreads();
    if (tid < Cc) {
        float s = 0.f;
        const float* r = sM + tid * Dd;
        #pragma unroll
        for (int d = 0; d < Dd; d++) s = fmaf(r[d], r[d], s);
        sMsq[tid] = s;
    }
    __syncthreads();

    float4 r[16];
    const float4* qrow = (const float4*)(qk + ((size_t)bh * Tt + tok) * Dd);
    #pragma unroll
    for (int i = 0; i < 16; i++) r[i] = qrow[i];
    float nsq = 0.f;
    #pragma unroll
    for (int i = 0; i < 16; i++)
        nsq += r[i].x * r[i].x + r[i].y * r[i].y + r[i].z * r[i].z + r[i].w * r[i].w;
    const float inv = 1.0f / fmaxf(sqrtf(nsq), 1e-12f);
    #pragma unroll
    for (int i = 0; i < 16; i++) {
        r[i].x *= inv; r[i].y *= inv; r[i].z *= inv; r[i].w *= inv;
    }

    float best = -3.402823e38f;
    int   bc   = 0;
    float* drow = g_dists + (size_t)bh * Cc * Tt + tok;

    #pragma unroll 2
    for (int c = 0; c < Cc; c++) {
        const float4* m4 = (const float4*)(sM + c * Dd);
        float a0 = 0.f, a1 = 0.f, a2 = 0.f, a3 = 0.f;
        #pragma unroll
        for (int i = 0; i < 16; i++) {
            float4 m = m4[i];
            a0 = fmaf(r[i].x, m.x, a0);
            a1 = fmaf(r[i].y, m.y, a1);
            a2 = fmaf(r[i].z, m.z, a2);
            a3 = fmaf(r[i].w, m.w, a3);
        }
        float dist = (a0 + a1) + (a2 + a3);
        drow[(size_t)c * Tt] = dist;
        if (dist > best) { best = dist; bc = c; }
    }

    sRed[tid] = nsq * inv * inv - 2.0f * best + sMsq[bc];
    __syncthreads();
    for (int s = 64; s > 0; s >>= 1) {
        if (tid < s) sRed[tid] += sRed[tid + s];
        __syncthreads();
    }
    if (tid == 0) atomicAdd(&g_loss, (double)sRed[0]);
}

// ------------------------------------------------------------------
// Phase 2: exact top-128 per row (unchanged)
// ------------------------------------------------------------------
__global__ void __launch_bounds__(256) k_topk()
{
    __shared__ unsigned sk[Tt];
    __shared__ unsigned hist[256];
    __shared__ unsigned warpagg[8];
    __shared__ unsigned warpbase[8];
    __shared__ unsigned s_pivot;
    __shared__ int      s_need;

    const int row = blockIdx.x;
    const int tid = threadIdx.x;
    const int lane = tid & 31;
    const int wrp  = tid >> 5;
    const float* src = g_dists + (size_t)row * Tt;

    for (int i = tid; i < Tt; i += 256) {
        unsigned u = __float_as_uint(src[i]);
        u ^= (u & 0x80000000u) ? 0xFFFFFFFFu : 0x80000000u;
        sk[i] = u;
    }

    unsigned prefix = 0;
    int remaining = Ww;
    for (int pass = 0; pass < 4; pass++) {
        const int shift = 24 - pass * 8;
        const unsigned himask = (pass == 0) ? 0u : (0xFFFFFFFFu << (shift + 8));
        hist[tid] = 0;
        __syncthreads();
        for (int i = tid; i < Tt; i += 256) {
            unsigned u = sk[i];
            bool act = ((u & himask) == prefix);
            unsigned am = __ballot_sync(0xFFFFFFFFu, act);
            if (act) {
                int bin = (u >> shift) & 255;
                unsigned m = __match_any_sync(am, bin);
                if (lane == __ffs(m) - 1)
                    atomicAdd(&hist[bin], (unsigned)__popc(m));
            }
        }
        __syncthreads();
        #pragma unroll
        for (int off = 1; off < 256; off <<= 1) {
            unsigned vc = hist[tid] + ((tid + off < 256) ? hist[tid + off] : 0u);
            __syncthreads();
            hist[tid] = vc;
            __syncthreads();
        }
        unsigned sb = hist[tid];
        unsigned sn = (tid == 255) ? 0u : hist[tid + 1];
        if (sb >= (unsigned)remaining && sn < (unsigned)remaining) {
            s_pivot = prefix | ((unsigned)tid << shift);
            s_need  = remaining - (int)sn;
        }
        __syncthreads();
        prefix    = s_pivot;
        remaining = s_need;
        __syncthreads();
    }
    const unsigned pivot = prefix;
    const int need_eq = remaining;

    int gt = 0, eq = 0;
    const int base = tid * 32;
    for (int j = 0; j < 32; j++) {
        unsigned u = sk[base + j];
        gt += (u > pivot);
        eq += (u == pivot);
    }
    unsigned pk = ((unsigned)gt << 16) | (unsigned)eq;
    unsigned x = pk;
    #pragma unroll
    for (int o = 1; o < 32; o <<= 1) {
        unsigned y = __shfl_up_sync(0xFFFFFFFFu, x, o);
        if (lane >= o) x += y;
    }
    if (lane == 31) warpagg[wrp] = x;
    __syncthreads();
    if (tid == 0) {
        unsigned a = 0;
        for (int i = 0; i < 8; i++) { unsigned t0 = warpagg[i]; warpbase[i] = a; a += t0; }
    }
    __syncthreads();
    unsigned excl = x - pk + warpbase[wrp];
    int gb = (int)(excl >> 16);
    int eb = (int)(excl & 0xFFFFu);

    int* outp = g_idx + row * Ww;
    for (int j = 0; j < 32; j++) {
        int e = base + j;
        unsigned u = sk[e];
        if (u > pivot) {
            outp[gb + min(eb, need_eq)] = e;
            gb++;
        } else if (u == pivot) {
            if (eb < need_eq) outp[gb + eb] = e;
            eb++;
        }
    }
}

// ------------------------------------------------------------------
// Phase 3: tensor-core attention; R11 = merged S+R loop, parallel
// sInv, interleaved softmax reductions.
//   A [0      ,  8704): Qhi            -> Vlo   (after SR)
//   B [8704   , 17408): Qlo            -> attn-lo rows (stride DP)
//   C [17408  , 26112): relw tf32
//   E [26112  , 34816): V raw          -> Vhi (in-place split)
//   D [34816  , 51712): scores/attn-hi (stride DP)
// ------------------------------------------------------------------
__global__ void __launch_bounds__(512, 1) k_attn(const float* __restrict__ qk,
                                                 const float* __restrict__ v,
                                                 const float* __restrict__ relw,
                                                 float* __restrict__ out)
{
    extern __shared__ float sm[];
    float* sA   = sm;
    float* sB   = sm + 8704;
    float* sC   = sm + 17408;
    float* sE   = sm + 26112;
    float* sD   = sm + 34816;
    float* sInv = sm + 51712;
    float* sRow = sInv + 128;
    int*   sIdx = (int*)(sRow + 128);
    float* sL   = sB;

    const int blk = blockIdx.x;
    const int bh  = blk >> 6;
    const int h   = bh & (Hh - 1);
    const int tid = threadIdx.x;
    const int l   = tid & 31;
    const int w   = tid >> 5;
    const int g   = l >> 2;
    const int t   = l & 3;

    if (tid < 128) sIdx[tid] = g_idx[blk * Ww + tid];
    __syncthreads();

    const float* qkb = qk + (size_t)bh * Tt * Dd;
    const float* vb  = v  + (size_t)bh * Tt * Dd;
    // gather: all LDG.128 issued up front (max MLP)
    {
        float4 qv[4], vv[4], rw[4];
        int ro[4], co[4];
        #pragma unroll
        for (int it = 0; it < 4; it++) {
            int gg = tid + it * 512;
            int r = gg >> 4, c4 = (gg & 15) << 2;
            ro[it] = r; co[it] = c4;
            int off = sIdx[r] * Dd + c4;
            qv[it] = *(const float4*)(qkb + off);
            vv[it] = *(const float4*)(vb + off);
            rw[it] = *(const float4*)(relw + (r * Hh + h) * Dd + c4);
        }
        #pragma unroll
        for (int it = 0; it < 4; it++) {
            float4 qh, ql;
            unsigned hi, lo;
            split_tf(qv[it].x, hi, lo); qh.x = __uint_as_float(hi); ql.x = __uint_as_float(lo);
            split_tf(qv[it].y, hi, lo); qh.y = __uint_as_float(hi); ql.y = __uint_as_float(lo);
            split_tf(qv[it].z, hi, lo); qh.z = __uint_as_float(hi); ql.z = __uint_as_float(lo);
            split_tf(qv[it].w, hi, lo); qh.w = __uint_as_float(hi); ql.w = __uint_as_float(lo);
            *(float4*)(sA + ro[it] * QP + co[it]) = qh;
            *(float4*)(sB + ro[it] * QP + co[it]) = ql;
            *(float4*)(sE + ro[it] * QP + co[it]) = vv[it];
            float4 rr = rw[it];
            rr.x = __uint_as_float(f2tf(rr.x * 0.125f));
            rr.y = __uint_as_float(f2tf(rr.y * 0.125f));
            rr.z = __uint_as_float(f2tf(rr.z * 0.125f));
            rr.w = __uint_as_float(f2tf(rr.w * 0.125f));
            *(float4*)(sC + ro[it] * QP + co[it]) = rr;
        }
    }
    __syncthreads();

    // ---- sInv: 4 threads per row, float4 loads, quad shfl-reduce ----
    {
        int row = tid >> 2, sub = tid & 3;
        const float4* rh = (const float4*)(sA + row * QP + sub * 16);
        const float4* rl = (const float4*)(sB + row * QP + sub * 16);
        float s = 0.f;
        #pragma unroll
        for (int i = 0; i < 4; i++) {
            float4 a = rh[i], b = rl[i];
            float q0 = a.x + b.x, q1 = a.y + b.y, q2 = a.z + b.z, q3 = a.w + b.w;
            s = fmaf(q0, q0, s); s = fmaf(q1, q1, s);
            s = fmaf(q2, q2, s); s = fmaf(q3, q3, s);
        }
        s += __shfl_xor_sync(0xFFFFFFFFu, s, 1);
        s += __shfl_xor_sync(0xFFFFFFFFu, s, 2);
        if (sub == 0) sInv[row] = 0.125f / fmaxf(sqrtf(s), 1e-12f);
    }
    __syncthreads();

    const int wm = w >> 2, wn = w & 3;
    const bool doR = (wm + wn >= 3);

    // ---- merged S + R compute (shared A-hi frags) ----
    {
        float accS[2][4][4];
        float accR[2][4][4];
        #pragma unroll
        for (int mt = 0; mt < 2; mt++)
            #pragma unroll
            for (int nt = 0; nt < 4; nt++)
                #pragma unroll
                for (int q = 0; q < 4; q++) { accS[mt][nt][q] = 0.f; accR[mt][nt][q] = 0.f; }

        #pragma unroll 1
        for (int kt = 0; kt < 8; kt++) {
            const int k0 = kt * 8;
            unsigned ahi[2][4], alo[2][4];
            #pragma unroll
            for (int mt = 0; mt < 2; mt++) {
                const int ro = (32 * wm + 16 * mt + g) * QP + k0 + t;
                ahi[mt][0] = FB(sA[ro]);              alo[mt][0] = FB(sB[ro]);
                ahi[mt][1] = FB(sA[ro + 8 * QP]);     alo[mt][1] = FB(sB[ro + 8 * QP]);
                ahi[mt][2] = FB(sA[ro + 4]);          alo[mt][2] = FB(sB[ro + 4]);
                ahi[mt][3] = FB(sA[ro + 8 * QP + 4]); alo[mt][3] = FB(sB[ro + 8 * QP + 4]);
            }
            unsigned bhi[4][2], blo[4][2];
            #pragma unroll
            for (int nt = 0; nt < 4; nt++) {
                const int ro = (32 * wn + 8 * nt + g) * QP + k0 + t;
                bhi[nt][0] = FB(sA[ro]);     blo[nt][0] = FB(sB[ro]);
                bhi[nt][1] = FB(sA[ro + 4]); blo[nt][1] = FB(sB[ro + 4]);
            }
            #pragma unroll
            for (int mt = 0; mt < 2; mt++)
                #pragma unroll
                for (int nt = 0; nt < 4; nt++) {
                    mma8(accS[mt][nt], ahi[mt], bhi[nt]);
                    mma8(accS[mt][nt], ahi[mt], blo[nt]);
                    mma8(accS[mt][nt], alo[mt], bhi[nt]);
                }
            if (doR) {
                unsigned br[4][2];
                #pragma unroll
                for (int nt = 0; nt < 4; nt++) {
                    const int ro = (32 * wn + 8 * nt + g) * QP + k0 + t;
                    br[nt][0] = FB(sC[ro]);
                    br[nt][1] = FB(sC[ro + 4]);
                }
                #pragma unroll
                for (int mt = 0; mt < 2; mt++)
                    #pragma unroll
                    for (int nt = 0; nt < 4; nt++)
                        mma8(accR[mt][nt], ahi[mt], br[nt]);
            }
        }
        // S epilogue
        #pragma unroll
        for (int mt = 0; mt < 2; mt++)
            #pragma unroll
            for (int nt = 0; nt < 4; nt++) {
                int row = 32 * wm + 16 * mt + g;
                int col = 32 * wn + 8 * nt + 2 * t;
                float s0 = sInv[col], s1 = sInv[col + 1];
                sD[row * DP + col]           = accS[mt][nt][0] * s0;
                sD[row * DP + col + 1]       = accS[mt][nt][1] * s1;
                sD[(row + 8) * DP + col]     = accS[mt][nt][2] * s0;
                sD[(row + 8) * DP + col + 1] = accS[mt][nt][3] * s1;
            }
        __syncthreads();
        // R fold epilogue (_shift): dots[p][p+r-127] += R[p][r]
        if (doR) {
            #pragma unroll
            for (int mt = 0; mt < 2; mt++)
                #pragma unroll
                for (int nt = 0; nt < 4; nt++) {
                    int p0r = 32 * wm + 16 * mt + g;
                    int col = 32 * wn + 8 * nt + 2 * t;
                    int qc0 = p0r + col - 127;
                    if (qc0 >= 0)     sD[p0r * DP + qc0]           += accR[mt][nt][0];
                    if (qc0 + 1 >= 0) sD[p0r * DP + qc0 + 1]       += accR[mt][nt][1];
                    int qc2 = p0r + 8 + col - 127;
                    if (qc2 >= 0)     sD[(p0r + 8) * DP + qc2]     += accR[mt][nt][2];
                    if (qc2 + 1 >= 0) sD[(p0r + 8) * DP + qc2 + 1] += accR[mt][nt][3];
                }
        }
    }

    // ---- V split (same phase as R fold: disjoint regions) ----
    {
        float4 vv[4];
        int ro[4], co[4];
        #pragma unroll
        for (int it = 0; it < 4; it++) {
            int gg = tid + it * 512;
            int r = gg >> 4, c4 = (gg & 15) << 2;
            ro[it] = r; co[it] = c4;
            vv[it] = *(float4*)(sE + r * QP + c4);
        }
        #pragma unroll
        for (int it = 0; it < 4; it++) {
            float4 vh, vl;
            unsigned hi, lo;
            split_tf(vv[it].x, hi, lo); vh.x = __uint_as_float(hi); vl.x = __uint_as_float(lo);
            split_tf(vv[it].y, hi, lo); vh.y = __uint_as_float(hi); vl.y = __uint_as_float(lo);
            split_tf(vv[it].z, hi, lo); vh.z = __uint_as_float(hi); vl.z = __uint_as_float(lo);
            split_tf(vv[it].w, hi, lo); vh.w = __uint_as_float(hi); vl.w = __uint_as_float(lo);
            *(float4*)(sE + ro[it] * QP + co[it]) = vh;
            *(float4*)(sA + ro[it] * QP + co[it]) = vl;
        }
    }
    __syncthreads();

    // ---- diag mask + softmax (8 rows per warp, interleaved trees) ----
    const int p0 = 8 * w;
    if (l < 8) sD[(p0 + l) * DP + (p0 + l)] = -50000.0f;
    __syncwarp();
    {
        float vv[8][4], mx[8], sum[8];
        #pragma unroll
        for (int i = 0; i < 8; i++) {
            mx[i] = -3.402823e38f;
            #pragma unroll
            for (int j = 0; j < 4; j++) {
                vv[i][j] = sD[(p0 + i) * DP + l + 32 * j];
                mx[i] = fmaxf(mx[i], vv[i][j]);
            }
        }
        #pragma unroll
        for (int o = 16; o > 0; o >>= 1)
            #pragma unroll
            for (int i = 0; i < 8; i++)
                mx[i] = fmaxf(mx[i], __shfl_xor_sync(0xffffffffu, mx[i], o));
        #pragma unroll
        for (int i = 0; i < 8; i++) {
            sum[i] = 0.f;
            #pragma unroll
            for (int j = 0; j < 4; j++) {
                float e = __expf(vv[i][j] - mx[i]);
                sum[i] += e;
                unsigned hi, lo;
                split_tf(e, hi, lo);
                sD[(p0 + i) * DP + l + 32 * j] = __uint_as_float(hi);
                sL[(p0 + i) * DP + l + 32 * j] = __uint_as_float(lo);
            }
        }
        #pragma unroll
        for (int o = 16; o > 0; o >>= 1)
            #pragma unroll
            for (int i = 0; i < 8; i++)
                sum[i] += __shfl_xor_sync(0xffffffffu, sum[i], o);
        if (l == 0) {
            #pragma unroll
            for (int i = 0; i < 8; i++) sRow[p0 + i] = 1.0f / sum[i];
        }
    }
    if (l < 8) atomicAdd(&g_cnt[bh * Tt + sIdx[p0 + l]], 1.0f);
    __syncthreads();

    // ---- O = attn.V (3xTF32), software-pipelined kt, scatter ----
    {
        const int om = w >> 1, on = w & 1;
        float acc[4][4];
        #pragma unroll
        for (int nt = 0; nt < 4; nt++)
            #pragma unroll
            for (int q = 0; q < 4; q++) acc[nt][q] = 0.f;

        #pragma unroll 2
        for (int kt = 0; kt < 16; kt++) {
            const int k0 = kt * 8;
            unsigned ahi[4], alo[4];
            const int ro = (16 * om + g) * DP + k0 + t;
            ahi[0] = FB(sD[ro]);              alo[0] = FB(sL[ro]);
            ahi[1] = FB(sD[ro + 8 * DP]);     alo[1] = FB(sL[ro + 8 * DP]);
            ahi[2] = FB(sD[ro + 4]);          alo[2] = FB(sL[ro + 4]);
            ahi[3] = FB(sD[ro + 8 * DP + 4]); alo[3] = FB(sL[ro + 8 * DP + 4]);
            unsigned bhi[4][2], blo[4][2];
            #pragma unroll
            for (int nt = 0; nt < 4; nt++) {
                int col = 32 * on + 8 * nt + g;
                bhi[nt][0] = FB(sE[(k0 + t) * QP + col]);     blo[nt][0] = FB(sA[(k0 + t) * QP + col]);
                bhi[nt][1] = FB(sE[(k0 + t + 4) * QP + col]); blo[nt][1] = FB(sA[(k0 + t + 4) * QP + col]);
            }
            #pragma unroll
            for (int nt = 0; nt < 4; nt++) {
                mma8(acc[nt], ahi, bhi[nt]);
                mma8(acc[nt], ahi, blo[nt]);
                mma8(acc[nt], alo, bhi[nt]);
            }
        }
        int row = 16 * om + g;
        float r0 = sRow[row], r1 = sRow[row + 8];
        float* d0 = out + ((size_t)bh * Tt + sIdx[row]) * Dd;
        float* d1 = out + ((size_t)bh * Tt + sIdx[row + 8]) * Dd;
        #pragma unroll
        for (int nt = 0; nt < 4; nt++) {
            int col = 32 * on + 8 * nt + 2 * t;
            atomicAdd(d0 + col,     acc[nt][0] * r0);
            atomicAdd(d0 + col + 1, acc[nt][1] * r0);
            atomicAdd(d1 + col,     acc[nt][2] * r1);
            atomicAdd(d1 + col + 1, acc[nt][3] * r1);
        }
    }
}

// ------------------------------------------------------------------
// Phase 4: out = num / (count + eps); append loss scalar (unchanged)
// ------------------------------------------------------------------
__global__ void __launch_bounds__(256) k_final(float* __restrict__ out, int out_size)
{
    int i = blockIdx.x * blockDim.x + threadIdx.x;
    if (i < NOUT / 4) {
        float c  = g_cnt[i >> 4];
        float rs = 1.0f / (c + 1e-5f);
        float4* p = (float4*)out + i;
        float4 vv = *p;
        vv.x *= rs; vv.y *= rs; vv.z *= rs; vv.w *= rs;
        *p = vv;
    }
    if (i == 0 && out_size > NOUT) {
        out[NOUT] = (float)(g_loss * (1.0e-4 / (double)NOUT));
    }
}

extern "C" void kernel_launch(void* const* d_in, const int* in_sizes, int n_in,
                              void* d_out, int out_size)
{
    const float* qk    = (const float*)d_in[0];
    const float* v     = (const float*)d_in[1];
    const float* means = (const float*)d_in[2];
    const float* relw  = (const float*)d_in[3];
    float* out = (float*)d_out;

    cudaMemsetAsync(d_out, 0, (size_t)out_size * sizeof(float));
    void* cp = 0; cudaGetSymbolAddress(&cp, g_cnt);
    cudaMemsetAsync(cp, 0, (size_t)BH * Tt * sizeof(float));
    void* lp = 0; cudaGetSymbolAddress(&lp, g_loss);
    cudaMemsetAsync(lp, 0, sizeof(double));

    dim3 g1(Tt / 128, BH);
    k_dists<<<g1, 128>>>(qk, means);

    k_topk<<<NROW, 256>>>();

    const int smem_attn = (51712 + 128 + 128 + 128) * 4;
    cudaFuncSetAttribute(k_attn, cudaFuncAttributeMaxDynamicSharedMemorySize, smem_attn);
    k_attn<<<NROW, 512, smem_attn>>>(qk, v, relw, out);

    k_final<<<NOUT / 4 / 256, 256>>>(out, out_size);
}

// round 14
// speedup vs baseline: 1.4097x; 1.0974x over previous
#include <cuda_runtime.h>
#include <cuda_bf16.h>
#include <math.h>

#define Bb   4
#define Hh   8
#define Tt   8192
#define Dd   64
#define Cc   64
#define Ww   128
#define BH   (Bb*Hh)
#define NROW (BH*Cc)
#define NOUT (BH*Tt*Dd)

__device__ float  g_dists[(size_t)NROW * Tt];
__device__ int    g_idx[NROW * Ww];
__device__ float  g_cnt[BH * Tt];
__device__ double g_loss;

// ---- bf16 helpers ------------------------------------------------
__device__ __forceinline__ unsigned pk2(float lo, float hi) {   // lower half = lo (first k elem)
    unsigned r;
    asm("cvt.rn.bf16x2.f32 %0, %1, %2;" : "=r"(r) : "f"(hi), "f"(lo));
    return r;
}
__device__ __forceinline__ void bsplit(float x, float &h, float &l) {
    __nv_bfloat16 b = __float2bfloat16(x);
    h = __bfloat162float(b);
    l = x - h;
}
// D += A(16x16) * B(16x8), bf16 inputs, f32 accum
__device__ __forceinline__ void mma16(float* c, const unsigned* a, const unsigned* b) {
    asm("mma.sync.aligned.m16n8k16.row.col.f32.bf16.bf16.f32 "
        "{%0,%1,%2,%3}, {%4,%5,%6,%7}, {%8,%9}, {%0,%1,%2,%3};"
        : "+f"(c[0]), "+f"(c[1]), "+f"(c[2]), "+f"(c[3])
        : "r"(a[0]), "r"(a[1]), "r"(a[2]), "r"(a[3]), "r"(b[0]), "r"(b[1]));
}

// ------------------------------------------------------------------
// Phase 1: dists = l2norm(qk) @ means^T (bit-identical, do not touch)
// ------------------------------------------------------------------
__global__ void __launch_bounds__(128) k_dists(const float* __restrict__ qk,
                                               const float* __restrict__ means)
{
    __shared__ float sM[Cc * Dd];
    __shared__ float sMsq[Cc];
    __shared__ float sRed[128];

    const int bh  = blockIdx.y;
    const int h   = bh & (Hh - 1);
    const int tid = threadIdx.x;
    const int tok = blockIdx.x * 128 + tid;

    {
        const float4* src = (const float4*)(means + (size_t)h * Cc * Dd);
        float4* dst = (float4*)sM;
        for (int g = tid; g < Cc * Dd / 4; g += 128) dst[g] = src[g];
    }
    __syncthreads();
    if (tid < Cc) {
        float s = 0.f;
        const float* r = sM + tid * Dd;
        #pragma unroll
        for (int d = 0; d < Dd; d++) s = fmaf(r[d], r[d], s);
        sMsq[tid] = s;
    }
    __syncthreads();

    float4 r[16];
    const float4* qrow = (const float4*)(qk + ((size_t)bh * Tt + tok) * Dd);
    #pragma unroll
    for (int i = 0; i < 16; i++) r[i] = qrow[i];
    float nsq = 0.f;
    #pragma unroll
    for (int i = 0; i < 16; i++)
        nsq += r[i].x * r[i].x + r[i].y * r[i].y + r[i].z * r[i].z + r[i].w * r[i].w;
    const float inv = 1.0f / fmaxf(sqrtf(nsq), 1e-12f);
    #pragma unroll
    for (int i = 0; i < 16; i++) {
        r[i].x *= inv; r[i].y *= inv; r[i].z *= inv; r[i].w *= inv;
    }

    float best = -3.402823e38f;
    int   bc   = 0;
    float* drow = g_dists + (size_t)bh * Cc * Tt + tok;

    #pragma unroll 2
    for (int c = 0; c < Cc; c++) {
        const float4* m4 = (const float4*)(sM + c * Dd);
        float a0 = 0.f, a1 = 0.f, a2 = 0.f, a3 = 0.f;
        #pragma unroll
        for (int i = 0; i < 16; i++) {
            float4 m = m4[i];
            a0 = fmaf(r[i].x, m.x, a0);
            a1 = fmaf(r[i].y, m.y, a1);
            a2 = fmaf(r[i].z, m.z, a2);
            a3 = fmaf(r[i].w, m.w, a3);
        }
        float dist = (a0 + a1) + (a2 + a3);
        drow[(size_t)c * Tt] = dist;
        if (dist > best) { best = dist; bc = c; }
    }

    sRed[tid] = nsq * inv * inv - 2.0f * best + sMsq[bc];
    __syncthreads();
    for (int s = 64; s > 0; s >>= 1) {
        if (tid < s) sRed[tid] += sRed[tid + s];
        __syncthreads();
    }
    if (tid == 0) atomicAdd(&g_loss, (double)sRed[0]);
}

// ------------------------------------------------------------------
// Phase 2: exact top-128 per row; 512 threads (selection identical)
// ------------------------------------------------------------------
__global__ void __launch_bounds__(512) k_topk()
{
    __shared__ unsigned sk[Tt];
    __shared__ unsigned hist[256];
    __shared__ unsigned warpagg[16];
    __shared__ unsigned warpbase[16];
    __shared__ unsigned s_pivot;
    __shared__ int      s_need;

    const int row = blockIdx.x;
    const int tid = threadIdx.x;
    const int lane = tid & 31;
    const int wrp  = tid >> 5;
    const float* src = g_dists + (size_t)row * Tt;

    for (int i = tid; i < Tt; i += 512) {
        unsigned u = __float_as_uint(src[i]);
        u ^= (u & 0x80000000u) ? 0xFFFFFFFFu : 0x80000000u;
        sk[i] = u;
    }

    unsigned prefix = 0;
    int remaining = Ww;
    for (int pass = 0; pass < 4; pass++) {
        const int shift = 24 - pass * 8;
        const unsigned himask = (pass == 0) ? 0u : (0xFFFFFFFFu << (shift + 8));
        if (tid < 256) hist[tid] = 0;
        __syncthreads();
        for (int i = tid; i < Tt; i += 512) {
            unsigned u = sk[i];
            bool act = ((u & himask) == prefix);
            unsigned am = __ballot_sync(0xFFFFFFFFu, act);
            if (act) {
                int bin = (u >> shift) & 255;
                unsigned m = __match_any_sync(am, bin);
                if (lane == __ffs(m) - 1)
                    atomicAdd(&hist[bin], (unsigned)__popc(m));
            }
        }
        __syncthreads();
        #pragma unroll
        for (int off = 1; off < 256; off <<= 1) {
            unsigned vc = 0;
            if (tid < 256) vc = hist[tid] + ((tid + off < 256) ? hist[tid + off] : 0u);
            __syncthreads();
            if (tid < 256) hist[tid] = vc;
            __syncthreads();
        }
        if (tid < 256) {
            unsigned sb = hist[tid];
            unsigned sn = (tid == 255) ? 0u : hist[tid + 1];
            if (sb >= (unsigned)remaining && sn < (unsigned)remaining) {
                s_pivot = prefix | ((unsigned)tid << shift);
                s_need  = remaining - (int)sn;
            }
        }
        __syncthreads();
        prefix    = s_pivot;
        remaining = s_need;
        __syncthreads();
    }
    const unsigned pivot = prefix;
    const int need_eq = remaining;

    int gt = 0, eq = 0;
    const int base = tid * 16;
    for (int j = 0; j < 16; j++) {
        unsigned u = sk[base + j];
        gt += (u > pivot);
        eq += (u == pivot);
    }
    unsigned pk = ((unsigned)gt << 16) | (unsigned)eq;
    unsigned x = pk;
    #pragma unroll
    for (int o = 1; o < 32; o <<= 1) {
        unsigned y = __shfl_up_sync(0xFFFFFFFFu, x, o);
        if (lane >= o) x += y;
    }
    if (lane == 31) warpagg[wrp] = x;
    __syncthreads();
    if (tid == 0) {
        unsigned a = 0;
        for (int i = 0; i < 16; i++) { unsigned t0 = warpagg[i]; warpbase[i] = a; a += t0; }
    }
    __syncthreads();
    unsigned excl = x - pk + warpbase[wrp];
    int gb = (int)(excl >> 16);
    int eb = (int)(excl & 0xFFFFu);

    int* outp = g_idx + row * Ww;
    for (int j = 0; j < 16; j++) {
        int e = base + j;
        unsigned u = sk[e];
        if (u > pivot) {
            outp[gb + min(eb, need_eq)] = e;
            gb++;
        } else if (u == pivot) {
            if (eb < need_eq) outp[gb + eb] = e;
            eb++;
        }
    }
}

// ------------------------------------------------------------------
// Phase 2.5: counts from indices + loss write
// ------------------------------------------------------------------
__global__ void __launch_bounds__(512) k_cnt(float* __restrict__ out, int out_size)
{
    int i = blockIdx.x * 512 + threadIdx.x;          // 262144 total
    int bh = i >> 13;                                // Cc*Ww = 8192 per bh
    atomicAdd(&g_cnt[bh * Tt + g_idx[i]], 1.0f);
    if (i == 0 && out_size > NOUT)
        out[NOUT] = (float)(g_loss * (1.0e-4 / (double)NOUT));
}

// ------------------------------------------------------------------
// Phase 3: bf16 split-precision tensor-core attention.
// SMEM word map (32-bit words):
//   QH 0      [128][36] Q-hi bf16x2     -> AH overlay after S/R
//   QL 4608   [128][36] Q-lo            -> AH/AL overlay
//   WH 9216   [128][36] relw-hi (x0.125)-> AL overlay
//   WL 13824  [128][36] relw-lo
//   VH 18432  [64][68]  V^T-hi (token pairs packed)
//   VL 22784  [64][68]  V^T-lo
//   D  27136  [128][132] scores fp32
//   AH 0      [128][68] attn-hi bf16x2 (overlay)
//   AL 8704   [128][68] attn-lo
//   tail: INV 44032, ROW 44160, CNT 44288, IDX 44416  (total 44544 words)
// ------------------------------------------------------------------
#define QH 0
#define QL 4608
#define WH 9216
#define WL 13824
#define VH 18432
#define VL 22784
#define DOFF 27136
#define AH 0
#define AL 8704

__global__ void __launch_bounds__(512, 1) k_attn(const float* __restrict__ qk,
                                                 const float* __restrict__ v,
                                                 const float* __restrict__ relw,
                                                 float* __restrict__ out)
{
    extern __shared__ float sm[];
    unsigned* usm = (unsigned*)sm;
    float* sD   = sm + DOFF;          // [128][132]
    float* sInv = sm + 44032;
    float* sRow = sm + 44160;
    float* sCnt = sm + 44288;
    int*   sIdx = (int*)(sm + 44416);

    const int blk = blockIdx.x;
    const int bh  = blk >> 6;
    const int h   = bh & (Hh - 1);
    const int tid = threadIdx.x;
    const int l   = tid & 31;
    const int w   = tid >> 5;
    const int g   = l >> 2;
    const int t   = l & 3;

    if (tid < 128) {
        int ix = g_idx[blk * Ww + tid];
        sIdx[tid] = ix;
        sInv[tid] = 0.f;
        sCnt[tid] = 1.0f / (g_cnt[bh * Tt + ix] + 1e-5f);
    }
    __syncthreads();

    const float* qkb = qk + (size_t)bh * Tt * Dd;
    const float* vb  = v  + (size_t)bh * Tt * Dd;
    // gather + split/pack (bf16). V stored transposed with token-pairs packed.
    {
        float4 qv[4], vv[4], rw[4];
        int ro[4], co[4];
        #pragma unroll
        for (int it = 0; it < 4; it++) {
            int gg = tid + it * 512;
            int r = gg >> 4, c4 = (gg & 15) << 2;
            ro[it] = r; co[it] = c4;
            int off = sIdx[r] * Dd + c4;
            qv[it] = *(const float4*)(qkb + off);
            vv[it] = *(const float4*)(vb + off);
            rw[it] = *(const float4*)(relw + (r * Hh + h) * Dd + c4);
        }
        #pragma unroll
        for (int it = 0; it < 4; it++) {
            int r = ro[it], c4 = co[it];
            float4 q = qv[it];
            atomicAdd(&sInv[r], q.x * q.x + q.y * q.y + q.z * q.z + q.w * q.w);
            float h0, l0, h1, l1, h2, l2, h3, l3;
            bsplit(q.x, h0, l0); bsplit(q.y, h1, l1);
            bsplit(q.z, h2, l2); bsplit(q.w, h3, l3);
            int qw = r * 36 + (c4 >> 1);
            usm[QH + qw]     = pk2(h0, h1);
            usm[QH + qw + 1] = pk2(h2, h3);
            usm[QL + qw]     = pk2(l0, l1);
            usm[QL + qw + 1] = pk2(l2, l3);
            float4 rr = rw[it];
            bsplit(rr.x * 0.125f, h0, l0); bsplit(rr.y * 0.125f, h1, l1);
            bsplit(rr.z * 0.125f, h2, l2); bsplit(rr.w * 0.125f, h3, l3);
            usm[WH + qw]     = pk2(h0, h1);
            usm[WH + qw + 1] = pk2(h2, h3);
            usm[WL + qw]     = pk2(l0, l1);
            usm[WL + qw + 1] = pk2(l2, l3);
            float4 vf = vv[it];
            float vh[4], vl[4];
            bsplit(vf.x, vh[0], vl[0]); bsplit(vf.y, vh[1], vl[1]);
            bsplit(vf.z, vh[2], vl[2]); bsplit(vf.w, vh[3], vl[3]);
            #pragma unroll
            for (int i = 0; i < 4; i++) {
                int col = c4 + i;
                size_t byh = ((size_t)(VH + col * 68 + (r >> 1)) << 2) + ((r & 1) << 1);
                *(__nv_bfloat16*)((char*)usm + byh) = __float2bfloat16(vh[i]);
                size_t byl = ((size_t)(VL + col * 68 + (r >> 1)) << 2) + ((r & 1) << 1);
                *(__nv_bfloat16*)((char*)usm + byl) = __float2bfloat16(vl[i]);
            }
        }
    }
    __syncthreads();
    if (tid < 128) sInv[tid] = 0.125f / fmaxf(sqrtf(sInv[tid]), 1e-12f);
    __syncthreads();

    const int wm = w >> 2, wn = w & 3;
    const bool doR = (wm + wn >= 3);

    // ---- merged S (3-pass bf16) + R (2-pass bf16), K=16 per mma ----
    {
        float accS[2][4][4];
        float accR[2][4][4];
        #pragma unroll
        for (int mt = 0; mt < 2; mt++)
            #pragma unroll
            for (int nt = 0; nt < 4; nt++)
                #pragma unroll
                for (int q = 0; q < 4; q++) { accS[mt][nt][q] = 0.f; accR[mt][nt][q] = 0.f; }

        #pragma unroll 1
        for (int kt = 0; kt < 4; kt++) {
            const int k0 = kt * 8;
            unsigned ah[2][4], al[2][4];
            #pragma unroll
            for (int mt = 0; mt < 2; mt++) {
                const int ro = (32 * wm + 16 * mt + g) * 36 + k0 + t;
                ah[mt][0] = usm[QH + ro];           al[mt][0] = usm[QL + ro];
                ah[mt][1] = usm[QH + ro + 8 * 36];  al[mt][1] = usm[QL + ro + 8 * 36];
                ah[mt][2] = usm[QH + ro + 4];       al[mt][2] = usm[QL + ro + 4];
                ah[mt][3] = usm[QH + ro + 8 * 36 + 4]; al[mt][3] = usm[QL + ro + 8 * 36 + 4];
            }
            unsigned bhx[4][2], blx[4][2];
            #pragma unroll
            for (int nt = 0; nt < 4; nt++) {
                const int ro = (32 * wn + 8 * nt + g) * 36 + k0 + t;
                bhx[nt][0] = usm[QH + ro];     blx[nt][0] = usm[QL + ro];
                bhx[nt][1] = usm[QH + ro + 4]; blx[nt][1] = usm[QL + ro + 4];
            }
            #pragma unroll
            for (int mt = 0; mt < 2; mt++)
                #pragma unroll
                for (int nt = 0; nt < 4; nt++) {
                    mma16(accS[mt][nt], ah[mt], bhx[nt]);
                    mma16(accS[mt][nt], ah[mt], blx[nt]);
                    mma16(accS[mt][nt], al[mt], bhx[nt]);
                }
            if (doR) {
                unsigned wh_[4][2], wl_[4][2];
                #pragma unroll
                for (int nt = 0; nt < 4; nt++) {
                    const int ro = (32 * wn + 8 * nt + g) * 36 + k0 + t;
                    wh_[nt][0] = usm[WH + ro];     wl_[nt][0] = usm[WL + ro];
                    wh_[nt][1] = usm[WH + ro + 4]; wl_[nt][1] = usm[WL + ro + 4];
                }
                #pragma unroll
                for (int mt = 0; mt < 2; mt++)
                    #pragma unroll
                    for (int nt = 0; nt < 4; nt++) {
                        mma16(accR[mt][nt], ah[mt], wh_[nt]);
                        mma16(accR[mt][nt], ah[mt], wl_[nt]);
                    }
            }
        }
        // S epilogue
        #pragma unroll
        for (int mt = 0; mt < 2; mt++)
            #pragma unroll
            for (int nt = 0; nt < 4; nt++) {
                int row = 32 * wm + 16 * mt + g;
                int col = 32 * wn + 8 * nt + 2 * t;
                float s0 = sInv[col], s1 = sInv[col + 1];
                sD[row * 132 + col]           = accS[mt][nt][0] * s0;
                sD[row * 132 + col + 1]       = accS[mt][nt][1] * s1;
                sD[(row + 8) * 132 + col]     = accS[mt][nt][2] * s0;
                sD[(row + 8) * 132 + col + 1] = accS[mt][nt][3] * s1;
            }
        __syncthreads();
        // R fold (_shift): dots[p][p+r-127] += R[p][r]
        if (doR) {
            #pragma unroll
            for (int mt = 0; mt < 2; mt++)
                #pragma unroll
                for (int nt = 0; nt < 4; nt++) {
                    int p0r = 32 * wm + 16 * mt + g;
                    int col = 32 * wn + 8 * nt + 2 * t;
                    int qc0 = p0r + col - 127;
                    if (qc0 >= 0)     sD[p0r * 132 + qc0]           += accR[mt][nt][0];
                    if (qc0 + 1 >= 0) sD[p0r * 132 + qc0 + 1]       += accR[mt][nt][1];
                    int qc2 = p0r + 8 + col - 127;
                    if (qc2 >= 0)     sD[(p0r + 8) * 132 + qc2]     += accR[mt][nt][2];
                    if (qc2 + 1 >= 0) sD[(p0r + 8) * 132 + qc2 + 1] += accR[mt][nt][3];
                }
        }
    }
    __syncthreads();

    // ---- diag mask + softmax; pack attn hi/lo to bf16 (overlays Q/W) ----
    const int p0 = 8 * w;
    if (l < 8) sD[(p0 + l) * 132 + (p0 + l)] = -50000.0f;
    __syncwarp();
    {
        float vv[8][4], mx[8], sum[8];
        #pragma unroll
        for (int i = 0; i < 8; i++) {
            mx[i] = -3.402823e38f;
            #pragma unroll
            for (int j = 0; j < 4; j++) {
                vv[i][j] = sD[(p0 + i) * 132 + l + 32 * j];
                mx[i] = fmaxf(mx[i], vv[i][j]);
            }
        }
        #pragma unroll
        for (int o = 16; o > 0; o >>= 1)
            #pragma unroll
            for (int i = 0; i < 8; i++)
                mx[i] = fmaxf(mx[i], __shfl_xor_sync(0xffffffffu, mx[i], o));
        #pragma unroll
        for (int i = 0; i < 8; i++) {
            sum[i] = 0.f;
            int p = p0 + i;
            #pragma unroll
            for (int j = 0; j < 4; j++) {
                float e = __expf(vv[i][j] - mx[i]);
                sum[i] += e;
                float eh, el;
                bsplit(e, eh, el);
                int c = l + 32 * j;
                size_t by = ((size_t)(p * 68 + (c >> 1)) << 2) + ((c & 1) << 1);
                *(__nv_bfloat16*)((char*)usm + (((size_t)AH) << 2) + by) = __float2bfloat16(eh);
                *(__nv_bfloat16*)((char*)usm + (((size_t)AL) << 2) + by) = __float2bfloat16(el);
            }
        }
        #pragma unroll
        for (int o = 16; o > 0; o >>= 1)
            #pragma unroll
            for (int i = 0; i < 8; i++)
                sum[i] += __shfl_xor_sync(0xffffffffu, sum[i], o);
        if (l == 0) {
            #pragma unroll
            for (int i = 0; i < 8; i++) sRow[p0 + i] = sCnt[p0 + i] / sum[i];
        }
    }
    __syncthreads();

    // ---- O = attn.V (3-pass bf16, K=16/mma), normalized scatter ----
    {
        const int om = w >> 1, on = w & 1;
        float acc[4][4];
        #pragma unroll
        for (int nt = 0; nt < 4; nt++)
            #pragma unroll
            for (int q = 0; q < 4; q++) acc[nt][q] = 0.f;

        #pragma unroll 2
        for (int kt = 0; kt < 8; kt++) {
            const int k0 = kt * 8;
            unsigned ah4[4], al4[4];
            const int ro = (16 * om + g) * 68 + k0 + t;
            ah4[0] = usm[AH + ro];            al4[0] = usm[AL + ro];
            ah4[1] = usm[AH + ro + 8 * 68];   al4[1] = usm[AL + ro + 8 * 68];
            ah4[2] = usm[AH + ro + 4];        al4[2] = usm[AL + ro + 4];
            ah4[3] = usm[AH + ro + 8 * 68 + 4]; al4[3] = usm[AL + ro + 8 * 68 + 4];
            unsigned bhx[4][2], blx[4][2];
            #pragma unroll
            for (int nt = 0; nt < 4; nt++) {
                const int ro2 = (32 * on + 8 * nt + g) * 68 + k0 + t;
                bhx[nt][0] = usm[VH + ro2];     blx[nt][0] = usm[VL + ro2];
                bhx[nt][1] = usm[VH + ro2 + 4]; blx[nt][1] = usm[VL + ro2 + 4];
            }
            #pragma unroll
            for (int nt = 0; nt < 4; nt++) {
                mma16(acc[nt], ah4, bhx[nt]);
                mma16(acc[nt], ah4, blx[nt]);
                mma16(acc[nt], al4, bhx[nt]);
            }
        }
        int row = 16 * om + g;
        float r0 = sRow[row], r1 = sRow[row + 8];
        float* d0 = out + ((size_t)bh * Tt + sIdx[row]) * Dd;
        float* d1 = out + ((size_t)bh * Tt + sIdx[row + 8]) * Dd;
        #pragma unroll
        for (int nt = 0; nt < 4; nt++) {
            int col = 32 * on + 8 * nt + 2 * t;
            atomicAdd(d0 + col,     acc[nt][0] * r0);
            atomicAdd(d0 + col + 1, acc[nt][1] * r0);
            atomicAdd(d1 + col,     acc[nt][2] * r1);
            atomicAdd(d1 + col + 1, acc[nt][3] * r1);
        }
    }
}

extern "C" void kernel_launch(void* const* d_in, const int* in_sizes, int n_in,
                              void* d_out, int out_size)
{
    const float* qk    = (const float*)d_in[0];
    const float* v     = (const float*)d_in[1];
    const float* means = (const float*)d_in[2];
    const float* relw  = (const float*)d_in[3];
    float* out = (float*)d_out;

    cudaMemsetAsync(d_out, 0, (size_t)out_size * sizeof(float));
    void* cp = 0; cudaGetSymbolAddress(&cp, g_cnt);
    cudaMemsetAsync(cp, 0, (size_t)BH * Tt * sizeof(float));
    void* lp = 0; cudaGetSymbolAddress(&lp, g_loss);
    cudaMemsetAsync(lp, 0, sizeof(double));

    dim3 g1(Tt / 128, BH);
    k_dists<<<g1, 128>>>(qk, means);

    k_topk<<<NROW, 512>>>();

    k_cnt<<<NROW * Ww / 512, 512>>>(out, out_size);

    const int smem_attn = 44544 * 4;    // 178,176 B
    cudaFuncSetAttribute(k_attn, cudaFuncAttributeMaxDynamicSharedMemorySize, smem_attn);
    k_attn<<<NROW, 512, smem_attn>>>(qk, v, relw, out);
}

// round 15
// speedup vs baseline: 1.4289x; 1.0136x over previous
#include <cuda_runtime.h>
#include <cuda_bf16.h>
#include <math.h>

#define Bb   4
#define Hh   8
#define Tt   8192
#define Dd   64
#define Cc   64
#define Ww   128
#define BH   (Bb*Hh)
#define NROW (BH*Cc)
#define NOUT (BH*Tt*Dd)

__device__ float  g_dists[(size_t)NROW * Tt];
__device__ int    g_idx[NROW * Ww];
__device__ float  g_cnt[BH * Tt];
__device__ double g_loss;

// ---- bf16 helpers ------------------------------------------------
__device__ __forceinline__ unsigned pk2(float lo, float hi) {   // lower half = lo (first k elem)
    unsigned r;
    asm("cvt.rn.bf16x2.f32 %0, %1, %2;" : "=r"(r) : "f"(hi), "f"(lo));
    return r;
}
__device__ __forceinline__ void bsplit(float x, float &h, float &l) {
    __nv_bfloat16 b = __float2bfloat16(x);
    h = __bfloat162float(b);
    l = x - h;
}
// D += A(16x16) * B(16x8), bf16 inputs, f32 accum
__device__ __forceinline__ void mma16(float* c, const unsigned* a, const unsigned* b) {
    asm("mma.sync.aligned.m16n8k16.row.col.f32.bf16.bf16.f32 "
        "{%0,%1,%2,%3}, {%4,%5,%6,%7}, {%8,%9}, {%0,%1,%2,%3};"
        : "+f"(c[0]), "+f"(c[1]), "+f"(c[2]), "+f"(c[3])
        : "r"(a[0]), "r"(a[1]), "r"(a[2]), "r"(a[3]), "r"(b[0]), "r"(b[1]));
}

// ------------------------------------------------------------------
// Phase 1: dists = l2norm(qk) @ means^T (bit-identical, do not touch)
// ------------------------------------------------------------------
__global__ void __launch_bounds__(128) k_dists(const float* __restrict__ qk,
                                               const float* __restrict__ means)
{
    __shared__ float sM[Cc * Dd];
    __shared__ float sMsq[Cc];
    __shared__ float sRed[128];

    const int bh  = blockIdx.y;
    const int h   = bh & (Hh - 1);
    const int tid = threadIdx.x;
    const int tok = blockIdx.x * 128 + tid;

    {
        const float4* src = (const float4*)(means + (size_t)h * Cc * Dd);
        float4* dst = (float4*)sM;
        for (int g = tid; g < Cc * Dd / 4; g += 128) dst[g] = src[g];
    }
    __syncthreads();
    if (tid < Cc) {
        float s = 0.f;
        const float* r = sM + tid * Dd;
        #pragma unroll
        for (int d = 0; d < Dd; d++) s = fmaf(r[d], r[d], s);
        sMsq[tid] = s;
    }
    __syncthreads();

    float4 r[16];
    const float4* qrow = (const float4*)(qk + ((size_t)bh * Tt + tok) * Dd);
    #pragma unroll
    for (int i = 0; i < 16; i++) r[i] = qrow[i];
    float nsq = 0.f;
    #pragma unroll
    for (int i = 0; i < 16; i++)
        nsq += r[i].x * r[i].x + r[i].y * r[i].y + r[i].z * r[i].z + r[i].w * r[i].w;
    const float inv = 1.0f / fmaxf(sqrtf(nsq), 1e-12f);
    #pragma unroll
    for (int i = 0; i < 16; i++) {
        r[i].x *= inv; r[i].y *= inv; r[i].z *= inv; r[i].w *= inv;
    }

    float best = -3.402823e38f;
    int   bc   = 0;
    float* drow = g_dists + (size_t)bh * Cc * Tt + tok;

    #pragma unroll 2
    for (int c = 0; c < Cc; c++) {
        const float4* m4 = (const float4*)(sM + c * Dd);
        float a0 = 0.f, a1 = 0.f, a2 = 0.f, a3 = 0.f;
        #pragma unroll
        for (int i = 0; i < 16; i++) {
            float4 m = m4[i];
            a0 = fmaf(r[i].x, m.x, a0);
            a1 = fmaf(r[i].y, m.y, a1);
            a2 = fmaf(r[i].z, m.z, a2);
            a3 = fmaf(r[i].w, m.w, a3);
        }
        float dist = (a0 + a1) + (a2 + a3);
        drow[(size_t)c * Tt] = dist;
        if (dist > best) { best = dist; bc = c; }
    }

    sRed[tid] = nsq * inv * inv - 2.0f * best + sMsq[bc];
    __syncthreads();
    for (int s = 64; s > 0; s >>= 1) {
        if (tid < s) sRed[tid] += sRed[tid + s];
        __syncthreads();
    }
    if (tid == 0) atomicAdd(&g_loss, (double)sRed[0]);
}

// ------------------------------------------------------------------
// Phase 2: exact top-128 per row; 512 threads (unchanged)
// ------------------------------------------------------------------
__global__ void __launch_bounds__(512) k_topk()
{
    __shared__ unsigned sk[Tt];
    __shared__ unsigned hist[256];
    __shared__ unsigned warpagg[16];
    __shared__ unsigned warpbase[16];
    __shared__ unsigned s_pivot;
    __shared__ int      s_need;

    const int row = blockIdx.x;
    const int tid = threadIdx.x;
    const int lane = tid & 31;
    const int wrp  = tid >> 5;
    const float* src = g_dists + (size_t)row * Tt;

    for (int i = tid; i < Tt; i += 512) {
        unsigned u = __float_as_uint(src[i]);
        u ^= (u & 0x80000000u) ? 0xFFFFFFFFu : 0x80000000u;
        sk[i] = u;
    }

    unsigned prefix = 0;
    int remaining = Ww;
    for (int pass = 0; pass < 4; pass++) {
        const int shift = 24 - pass * 8;
        const unsigned himask = (pass == 0) ? 0u : (0xFFFFFFFFu << (shift + 8));
        if (tid < 256) hist[tid] = 0;
        __syncthreads();
        for (int i = tid; i < Tt; i += 512) {
            unsigned u = sk[i];
            bool act = ((u & himask) == prefix);
            unsigned am = __ballot_sync(0xFFFFFFFFu, act);
            if (act) {
                int bin = (u >> shift) & 255;
                unsigned m = __match_any_sync(am, bin);
                if (lane == __ffs(m) - 1)
                    atomicAdd(&hist[bin], (unsigned)__popc(m));
            }
        }
        __syncthreads();
        #pragma unroll
        for (int off = 1; off < 256; off <<= 1) {
            unsigned vc = 0;
            if (tid < 256) vc = hist[tid] + ((tid + off < 256) ? hist[tid + off] : 0u);
            __syncthreads();
            if (tid < 256) hist[tid] = vc;
            __syncthreads();
        }
        if (tid < 256) {
            unsigned sb = hist[tid];
            unsigned sn = (tid == 255) ? 0u : hist[tid + 1];
            if (sb >= (unsigned)remaining && sn < (unsigned)remaining) {
                s_pivot = prefix | ((unsigned)tid << shift);
                s_need  = remaining - (int)sn;
            }
        }
        __syncthreads();
        prefix    = s_pivot;
        remaining = s_need;
        __syncthreads();
    }
    const unsigned pivot = prefix;
    const int need_eq = remaining;

    int gt = 0, eq = 0;
    const int base = tid * 16;
    for (int j = 0; j < 16; j++) {
        unsigned u = sk[base + j];
        gt += (u > pivot);
        eq += (u == pivot);
    }
    unsigned pk = ((unsigned)gt << 16) | (unsigned)eq;
    unsigned x = pk;
    #pragma unroll
    for (int o = 1; o < 32; o <<= 1) {
        unsigned y = __shfl_up_sync(0xFFFFFFFFu, x, o);
        if (lane >= o) x += y;
    }
    if (lane == 31) warpagg[wrp] = x;
    __syncthreads();
    if (tid == 0) {
        unsigned a = 0;
        for (int i = 0; i < 16; i++) { unsigned t0 = warpagg[i]; warpbase[i] = a; a += t0; }
    }
    __syncthreads();
    unsigned excl = x - pk + warpbase[wrp];
    int gb = (int)(excl >> 16);
    int eb = (int)(excl & 0xFFFFu);

    int* outp = g_idx + row * Ww;
    for (int j = 0; j < 16; j++) {
        int e = base + j;
        unsigned u = sk[e];
        if (u > pivot) {
            outp[gb + min(eb, need_eq)] = e;
            gb++;
        } else if (u == pivot) {
            if (eb < need_eq) outp[gb + eb] = e;
            eb++;
        }
    }
}

// ------------------------------------------------------------------
// Phase 2.5: counts from indices + loss write (unchanged)
// ------------------------------------------------------------------
__global__ void __launch_bounds__(512) k_cnt(float* __restrict__ out, int out_size)
{
    int i = blockIdx.x * 512 + threadIdx.x;
    int bh = i >> 13;
    atomicAdd(&g_cnt[bh * Tt + g_idx[i]], 1.0f);
    if (i == 0 && out_size > NOUT)
        out[NOUT] = (float)(g_loss * (1.0e-4 / (double)NOUT));
}

// ------------------------------------------------------------------
// Phase 3: bf16 split attention, now 1024 threads (32 warps) for 2x
// latency hiding at the same 1-block/SM smem footprint (178KB).
// SMEM word map unchanged from R14.
// ------------------------------------------------------------------
#define QH 0
#define QL 4608
#define WH 9216
#define WL 13824
#define VH 18432
#define VL 22784
#define DOFF 27136
#define AH 0
#define AL 8704

__global__ void __launch_bounds__(1024, 1) k_attn(const float* __restrict__ qk,
                                                  const float* __restrict__ v,
                                                  const float* __restrict__ relw,
                                                  float* __restrict__ out)
{
    extern __shared__ float sm[];
    unsigned* usm = (unsigned*)sm;
    float* sD   = sm + DOFF;          // [128][132]
    float* sInv = sm + 44032;
    float* sRow = sm + 44160;
    float* sCnt = sm + 44288;
    int*   sIdx = (int*)(sm + 44416);

    const int blk = blockIdx.x;
    const int bh  = blk >> 6;
    const int h   = bh & (Hh - 1);
    const int tid = threadIdx.x;
    const int l   = tid & 31;
    const int w   = tid >> 5;          // 0..31
    const int g   = l >> 2;
    const int t   = l & 3;

    if (tid < 128) {
        int ix = g_idx[blk * Ww + tid];
        sIdx[tid] = ix;
        sInv[tid] = 0.f;
        sCnt[tid] = 1.0f / (g_cnt[bh * Tt + ix] + 1e-5f);
    }
    __syncthreads();

    const float* qkb = qk + (size_t)bh * Tt * Dd;
    const float* vb  = v  + (size_t)bh * Tt * Dd;
    // gather + split/pack (bf16); V stored transposed (token pairs packed)
    {
        float4 qv[2], vv[2], rw[2];
        int ro[2], co[2];
        #pragma unroll
        for (int it = 0; it < 2; it++) {
            int gg = tid + it * 1024;
            int r = gg >> 4, c4 = (gg & 15) << 2;
            ro[it] = r; co[it] = c4;
            int off = sIdx[r] * Dd + c4;
            qv[it] = *(const float4*)(qkb + off);
            vv[it] = *(const float4*)(vb + off);
            rw[it] = *(const float4*)(relw + (r * Hh + h) * Dd + c4);
        }
        #pragma unroll
        for (int it = 0; it < 2; it++) {
            int r = ro[it], c4 = co[it];
            float4 q = qv[it];
            atomicAdd(&sInv[r], q.x * q.x + q.y * q.y + q.z * q.z + q.w * q.w);
            float h0, l0, h1, l1, h2, l2, h3, l3;
            bsplit(q.x, h0, l0); bsplit(q.y, h1, l1);
            bsplit(q.z, h2, l2); bsplit(q.w, h3, l3);
            int qw = r * 36 + (c4 >> 1);
            usm[QH + qw]     = pk2(h0, h1);
            usm[QH + qw + 1] = pk2(h2, h3);
            usm[QL + qw]     = pk2(l0, l1);
            usm[QL + qw + 1] = pk2(l2, l3);
            float4 rr = rw[it];
            bsplit(rr.x * 0.125f, h0, l0); bsplit(rr.y * 0.125f, h1, l1);
            bsplit(rr.z * 0.125f, h2, l2); bsplit(rr.w * 0.125f, h3, l3);
            usm[WH + qw]     = pk2(h0, h1);
            usm[WH + qw + 1] = pk2(h2, h3);
            usm[WL + qw]     = pk2(l0, l1);
            usm[WL + qw + 1] = pk2(l2, l3);
            float4 vf = vv[it];
            float vh[4], vl[4];
            bsplit(vf.x, vh[0], vl[0]); bsplit(vf.y, vh[1], vl[1]);
            bsplit(vf.z, vh[2], vl[2]); bsplit(vf.w, vh[3], vl[3]);
            #pragma unroll
            for (int i = 0; i < 4; i++) {
                int col = c4 + i;
                size_t byh = ((size_t)(VH + col * 68 + (r >> 1)) << 2) + ((r & 1) << 1);
                *(__nv_bfloat16*)((char*)usm + byh) = __float2bfloat16(vh[i]);
                size_t byl = ((size_t)(VL + col * 68 + (r >> 1)) << 2) + ((r & 1) << 1);
                *(__nv_bfloat16*)((char*)usm + byl) = __float2bfloat16(vl[i]);
            }
        }
    }
    __syncthreads();
    if (tid < 128) sInv[tid] = 0.125f / fmaxf(sqrtf(sInv[tid]), 1e-12f);
    __syncthreads();

    // ---- merged S (3-pass) + R (2-pass): 8x4 grid of 16x32 tiles ----
    {
        const int wm = w >> 2, wn = w & 3;
        const bool doR = (16 * wm + 32 * wn >= 81);

        float accS[4][4];
        float accR[4][4];
        #pragma unroll
        for (int nt = 0; nt < 4; nt++)
            #pragma unroll
            for (int q = 0; q < 4; q++) { accS[nt][q] = 0.f; accR[nt][q] = 0.f; }

        #pragma unroll 1
        for (int kt = 0; kt < 4; kt++) {
            const int k0 = kt * 8;
            unsigned ah[4], al[4];
            const int ro = (16 * wm + g) * 36 + k0 + t;
            ah[0] = usm[QH + ro];            al[0] = usm[QL + ro];
            ah[1] = usm[QH + ro + 8 * 36];   al[1] = usm[QL + ro + 8 * 36];
            ah[2] = usm[QH + ro + 4];        al[2] = usm[QL + ro + 4];
            ah[3] = usm[QH + ro + 8 * 36 + 4]; al[3] = usm[QL + ro + 8 * 36 + 4];
            #pragma unroll
            for (int nt = 0; nt < 4; nt++) {
                const int rob = (32 * wn + 8 * nt + g) * 36 + k0 + t;
                unsigned bh2[2], bl2[2];
                bh2[0] = usm[QH + rob]; bh2[1] = usm[QH + rob + 4];
                bl2[0] = usm[QL + rob]; bl2[1] = usm[QL + rob + 4];
                mma16(accS[nt], ah, bh2);
                mma16(accS[nt], ah, bl2);
                mma16(accS[nt], al, bh2);
                if (doR) {
                    unsigned wh2[2], wl2[2];
                    wh2[0] = usm[WH + rob]; wh2[1] = usm[WH + rob + 4];
                    wl2[0] = usm[WL + rob]; wl2[1] = usm[WL + rob + 4];
                    mma16(accR[nt], ah, wh2);
                    mma16(accR[nt], ah, wl2);
                }
            }
        }
        // S epilogue
        #pragma unroll
        for (int nt = 0; nt < 4; nt++) {
            int row = 16 * wm + g;
            int col = 32 * wn + 8 * nt + 2 * t;
            float s0 = sInv[col], s1 = sInv[col + 1];
            sD[row * 132 + col]           = accS[nt][0] * s0;
            sD[row * 132 + col + 1]       = accS[nt][1] * s1;
            sD[(row + 8) * 132 + col]     = accS[nt][2] * s0;
            sD[(row + 8) * 132 + col + 1] = accS[nt][3] * s1;
        }
        __syncthreads();
        // R fold (_shift): dots[p][p+r-127] += R[p][r]
        if (doR) {
            #pragma unroll
            for (int nt = 0; nt < 4; nt++) {
                int p0r = 16 * wm + g;
                int col = 32 * wn + 8 * nt + 2 * t;
                int qc0 = p0r + col - 127;
                if (qc0 >= 0)     sD[p0r * 132 + qc0]           += accR[nt][0];
                if (qc0 + 1 >= 0) sD[p0r * 132 + qc0 + 1]       += accR[nt][1];
                int qc2 = p0r + 8 + col - 127;
                if (qc2 >= 0)     sD[(p0r + 8) * 132 + qc2]     += accR[nt][2];
                if (qc2 + 1 >= 0) sD[(p0r + 8) * 132 + qc2 + 1] += accR[nt][3];
            }
        }
    }
    __syncthreads();

    // ---- diag mask + softmax: warp w owns rows 4w..4w+3 ----
    const int p0 = 4 * w;
    if (l < 4) sD[(p0 + l) * 132 + (p0 + l)] = -50000.0f;
    __syncwarp();
    {
        float vv[4][4], mx[4], sum[4];
        #pragma unroll
        for (int i = 0; i < 4; i++) {
            mx[i] = -3.402823e38f;
            #pragma unroll
            for (int j = 0; j < 4; j++) {
                vv[i][j] = sD[(p0 + i) * 132 + l + 32 * j];
                mx[i] = fmaxf(mx[i], vv[i][j]);
            }
        }
        #pragma unroll
        for (int o = 16; o > 0; o >>= 1)
            #pragma unroll
            for (int i = 0; i < 4; i++)
                mx[i] = fmaxf(mx[i], __shfl_xor_sync(0xffffffffu, mx[i], o));
        #pragma unroll
        for (int i = 0; i < 4; i++) {
            sum[i] = 0.f;
            int p = p0 + i;
            #pragma unroll
            for (int j = 0; j < 4; j++) {
                float e = __expf(vv[i][j] - mx[i]);
                sum[i] += e;
                float eh, el;
                bsplit(e, eh, el);
                int c = l + 32 * j;
                size_t by = ((size_t)(p * 68 + (c >> 1)) << 2) + ((c & 1) << 1);
                *(__nv_bfloat16*)((char*)usm + (((size_t)AH) << 2) + by) = __float2bfloat16(eh);
                *(__nv_bfloat16*)((char*)usm + (((size_t)AL) << 2) + by) = __float2bfloat16(el);
            }
        }
        #pragma unroll
        for (int o = 16; o > 0; o >>= 1)
            #pragma unroll
            for (int i = 0; i < 4; i++)
                sum[i] += __shfl_xor_sync(0xffffffffu, sum[i], o);
        if (l == 0) {
            #pragma unroll
            for (int i = 0; i < 4; i++) sRow[p0 + i] = sCnt[p0 + i] / sum[i];
        }
    }
    __syncthreads();

    // ---- O = attn.V (3-pass): 8x4 grid of 16x16 tiles ----
    {
        const int om = w >> 2, on = w & 3;
        float acc[2][4];
        #pragma unroll
        for (int nt = 0; nt < 2; nt++)
            #pragma unroll
            for (int q = 0; q < 4; q++) acc[nt][q] = 0.f;

        #pragma unroll 2
        for (int kt = 0; kt < 8; kt++) {
            const int k0 = kt * 8;
            unsigned ah4[4], al4[4];
            const int ro = (16 * om + g) * 68 + k0 + t;
            ah4[0] = usm[AH + ro];              al4[0] = usm[AL + ro];
            ah4[1] = usm[AH + ro + 8 * 68];     al4[1] = usm[AL + ro + 8 * 68];
            ah4[2] = usm[AH + ro + 4];          al4[2] = usm[AL + ro + 4];
            ah4[3] = usm[AH + ro + 8 * 68 + 4]; al4[3] = usm[AL + ro + 8 * 68 + 4];
            #pragma unroll
            for (int nt = 0; nt < 2; nt++) {
                const int ro2 = (16 * on + 8 * nt + g) * 68 + k0 + t;
                unsigned bh2[2], bl2[2];
                bh2[0] = usm[VH + ro2]; bh2[1] = usm[VH + ro2 + 4];
                bl2[0] = usm[VL + ro2]; bl2[1] = usm[VL + ro2 + 4];
                mma16(acc[nt], ah4, bh2);
                mma16(acc[nt], ah4, bl2);
                mma16(acc[nt], al4, bh2);
            }
        }
        int row = 16 * om + g;
        float r0 = sRow[row], r1 = sRow[row + 8];
        float* d0 = out + ((size_t)bh * Tt + sIdx[row]) * Dd;
        float* d1 = out + ((size_t)bh * Tt + sIdx[row + 8]) * Dd;
        #pragma unroll
        for (int nt = 0; nt < 2; nt++) {
            int col = 16 * on + 8 * nt + 2 * t;
            atomicAdd(d0 + col,     acc[nt][0] * r0);
            atomicAdd(d0 + col + 1, acc[nt][1] * r0);
            atomicAdd(d1 + col,     acc[nt][2] * r1);
            atomicAdd(d1 + col + 1, acc[nt][3] * r1);
        }
    }
}

extern "C" void kernel_launch(void* const* d_in, const int* in_sizes, int n_in,
                              void* d_out, int out_size)
{
    const float* qk    = (const float*)d_in[0];
    const float* v     = (const float*)d_in[1];
    const float* means = (const float*)d_in[2];
    const float* relw  = (const float*)d_in[3];
    float* out = (float*)d_out;

    cudaMemsetAsync(d_out, 0, (size_t)out_size * sizeof(float));
    void* cp = 0; cudaGetSymbolAddress(&cp, g_cnt);
    cudaMemsetAsync(cp, 0, (size_t)BH * Tt * sizeof(float));
    void* lp = 0; cudaGetSymbolAddress(&lp, g_loss);
    cudaMemsetAsync(lp, 0, sizeof(double));

    dim3 g1(Tt / 128, BH);
    k_dists<<<g1, 128>>>(qk, means);

    k_topk<<<NROW, 512>>>();

    k_cnt<<<NROW * Ww / 512, 512>>>(out, out_size);

    const int smem_attn = 44544 * 4;    // 178,176 B
    cudaFuncSetAttribute(k_attn, cudaFuncAttributeMaxDynamicSharedMemorySize, smem_attn);
    k_attn<<<NROW, 1024, smem_attn>>>(qk, v, relw, out);
}